// round 5
// baseline (speedup 1.0000x reference)
#include <cuda_runtime.h>
#include <math.h>

// ---------------- problem constants ----------------
constexpr int NU = 100000, NM = 20000;
constexpr int FU = 32, FM = 128;
constexpr int H1 = 8, C1 = 16, D1 = 128;   // layer 1
constexpr int H2 = 4, C2 = 128, D2 = 512;  // layer 2
constexpr int E = 250000, EL = 200000;
constexpr int HID = 16;

// ---------------- device scratch (static; no allocs allowed) ----------------
__device__ float g_hs1um[(size_t)NU * D1];
__device__ float g_hs1mu[(size_t)NM * D1];
__device__ float g_hs2mu[(size_t)NM * D2];
__device__ float g_agg[(size_t)NM * D2];
__device__ float g_zu[(size_t)NU * D1];
__device__ float g_zm[(size_t)NM * D1];
__device__ float g_zm2[(size_t)NM * D2];
__device__ float g_pu[(size_t)NU * HID];
__device__ float g_pm[(size_t)NM * HID];
__device__ float g_su1[(size_t)NU * H1];
__device__ float g_su2[(size_t)NU * H1];
__device__ float g_sm1[(size_t)NM * H1];
__device__ float g_sm2[(size_t)NM * H1];
__device__ float g_wa1[FM * H1];
__device__ float g_wa2[FM * H1];
__device__ float g_wa3[FM * H1];
__device__ float g_wa4[FM * H1];
// CSR
__device__ int g_rp_um[NM + 1];
__device__ int g_rp_mu[NU + 1];
__device__ int g_csr_um[E];
__device__ int g_csr_mu[E];
__device__ int g_cnt_um[NM];
__device__ int g_cnt_mu[NU];
__device__ int g_bsum[256];

static inline int ceil_div(int a, int b) { return (a + b - 1) / b; }

// ================= CSR build =================
__global__ void hist2_k(const int* __restrict__ d1, const int* __restrict__ d2,
                        int* __restrict__ c1, int* __restrict__ c2, int ne) {
    int e = blockIdx.x * blockDim.x + threadIdx.x;
    if (e >= ne) return;
    atomicAdd(&c1[d1[e]], 1);
    atomicAdd(&c2[d2[e]], 1);
}

__global__ void blk_reduce_k(const int* __restrict__ deg, int* __restrict__ bsum, int n) {
    __shared__ int sh[256];
    int b = blockIdx.x, tid = threadIdx.x;
    int base = b * 1024;
    int s = 0;
    for (int i = tid; i < 1024; i += 256) {
        int idx = base + i;
        if (idx < n) s += deg[idx];
    }
    sh[tid] = s; __syncthreads();
    for (int o = 128; o; o >>= 1) { if (tid < o) sh[tid] += sh[tid + o]; __syncthreads(); }
    if (tid == 0) bsum[b] = sh[0];
}

__global__ void scan_bsum_k(int* __restrict__ bsum, int nb) {
    if (threadIdx.x == 0) {
        int acc = 0;
        for (int i = 0; i < nb; i++) { int v = bsum[i]; bsum[i] = acc; acc += v; }
    }
}

__global__ void blk_scan_k(const int* __restrict__ deg, const int* __restrict__ bsum,
                           int* __restrict__ rowptr, int n, int ne) {
    __shared__ int ts[256];
    int b = blockIdx.x, tid = threadIdx.x;
    int base = b * 1024 + tid * 4;
    int v[4]; int loc = 0;
#pragma unroll
    for (int j = 0; j < 4; j++) { int idx = base + j; v[j] = (idx < n) ? deg[idx] : 0; loc += v[j]; }
    ts[tid] = loc; __syncthreads();
    for (int o = 1; o < 256; o <<= 1) {
        int t = (tid >= o) ? ts[tid - o] : 0;
        __syncthreads();
        ts[tid] += t;
        __syncthreads();
    }
    int excl = ts[tid] - loc + bsum[b];
#pragma unroll
    for (int j = 0; j < 4; j++) {
        int idx = base + j;
        if (idx < n) rowptr[idx] = excl;
        excl += v[j];
    }
    if (b == 0 && tid == 0) rowptr[n] = ne;
}

__global__ void scatter2_k(const int* __restrict__ s1, const int* __restrict__ d1,
                           const int* __restrict__ rp1, int* __restrict__ c1, int* __restrict__ o1,
                           const int* __restrict__ s2, const int* __restrict__ d2,
                           const int* __restrict__ rp2, int* __restrict__ c2, int* __restrict__ o2,
                           int ne) {
    int e = blockIdx.x * blockDim.x + threadIdx.x;
    if (e >= ne) return;
    { int d = d1[e]; int p = rp1[d] + atomicAdd(&c1[d], 1); o1[p] = s1[e]; }
    { int d = d2[e]; int p = rp2[d] + atomicAdd(&c2[d], 1); o2[p] = s2[e]; }
}

// ================= fold W @ a -> wa[K,H] =================
__global__ void fold_k(const float* __restrict__ W, const float* __restrict__ a,
                       float* __restrict__ wa, int K, int H, int C) {
    int t = blockIdx.x * blockDim.x + threadIdx.x;
    if (t >= K * H) return;
    int k = t / H, h = t - k * H;
    float s = 0.f;
    for (int c = 0; c < C; c++) s += W[(size_t)k * H * C + h * C + c] * a[h * C + c];
    wa[t] = s;
}

// ====== scores: read x once, produce y1 = x@wa1, y2 = x@wa2 (warp per node) =====
template <int K, int H>
__global__ void scores2_k(const float* __restrict__ x,
                          const float* __restrict__ wa1, const float* __restrict__ wa2,
                          float* __restrict__ y1, float* __restrict__ y2, int n) {
    __shared__ float s1[K * H], s2[K * H];
    int t = threadIdx.x;
    for (int i = t; i < K * H; i += blockDim.x) { s1[i] = wa1[i]; s2[i] = wa2[i]; }
    __syncthreads();
    int warp = t >> 5, lane = t & 31;
    int node = blockIdx.x * (blockDim.x >> 5) + warp;
    if (node >= n) return;
    const float* row = x + (size_t)node * K;
    float a1[H] = {}, a2[H] = {};
#pragma unroll
    for (int k0 = 0; k0 < K; k0 += 32) {
        float xv = row[k0 + lane];
#pragma unroll
        for (int h = 0; h < H; h++) {
            a1[h] += xv * s1[(k0 + lane) * H + h];
            a2[h] += xv * s2[(k0 + lane) * H + h];
        }
    }
#pragma unroll
    for (int h = 0; h < H; h++) {
#pragma unroll
        for (int o = 16; o; o >>= 1) {
            a1[h] += __shfl_xor_sync(0xffffffffu, a1[h], o);
            a2[h] += __shfl_xor_sync(0xffffffffu, a2[h], o);
        }
    }
    if (lane == 0) {
#pragma unroll
        for (int h = 0; h < H; h++) {
            y1[(size_t)node * H + h] = a1[h];
            y2[(size_t)node * H + h] = a2[h];
        }
    }
}

// ====== fused GAT aggregation (GEMM-first): warp per dst, no atomics ======
template <int H, int C>
__global__ void gat_aggr_k(const int* __restrict__ rowptr, const int* __restrict__ csr,
                           const float* __restrict__ es, const float* __restrict__ ed,
                           const float* __restrict__ feat, const float* __restrict__ bias,
                           float* __restrict__ out, int nd, int relu) {
    constexpr int D = H * C;
    constexpr int NV = D / 128;
    int w = (blockIdx.x * blockDim.x + threadIdx.x) >> 5;
    int lane = threadIdx.x & 31;
    if (w >= nd) return;
    int rs = rowptr[w], re = rowptr[w + 1];
    float edv[H], m[H], ssum[H];
#pragma unroll
    for (int h = 0; h < H; h++) { edv[h] = ed[(size_t)w * H + h]; m[h] = -INFINITY; ssum[h] = 0.f; }
    for (int i = rs + lane; i < re; i += 32) {
        int s = csr[i];
#pragma unroll
        for (int h = 0; h < H; h++) {
            float e = es[(size_t)s * H + h] + edv[h];
            e = e > 0.f ? e : 0.2f * e;
            m[h] = fmaxf(m[h], e);
        }
    }
#pragma unroll
    for (int h = 0; h < H; h++)
#pragma unroll
        for (int o = 16; o; o >>= 1) m[h] = fmaxf(m[h], __shfl_xor_sync(0xffffffffu, m[h], o));
    for (int i = rs + lane; i < re; i += 32) {
        int s = csr[i];
#pragma unroll
        for (int h = 0; h < H; h++) {
            float e = es[(size_t)s * H + h] + edv[h];
            e = e > 0.f ? e : 0.2f * e;
            ssum[h] += __expf(e - m[h]);
        }
    }
#pragma unroll
    for (int h = 0; h < H; h++) {
#pragma unroll
        for (int o = 16; o; o >>= 1) ssum[h] += __shfl_xor_sync(0xffffffffu, ssum[h], o);
        ssum[h] = 1.f / (ssum[h] + 1e-16f);
    }
    float4 acc[NV];
#pragma unroll
    for (int v = 0; v < NV; v++) acc[v] = make_float4(0.f, 0.f, 0.f, 0.f);
#pragma unroll 2
    for (int i = rs; i < re; i++) {
        int s = csr[i];
#pragma unroll
        for (int v = 0; v < NV; v++) {
            int h = (v * 128 + lane * 4) / C;
            float e = es[(size_t)s * H + h] + edv[h];
            e = e > 0.f ? e : 0.2f * e;
            float a = __expf(e - m[h]) * ssum[h];
            float4 x = *(const float4*)&feat[(size_t)s * D + v * 128 + lane * 4];
            acc[v].x += a * x.x; acc[v].y += a * x.y;
            acc[v].z += a * x.z; acc[v].w += a * x.w;
        }
    }
#pragma unroll
    for (int v = 0; v < NV; v++) {
        float4 bb = *(const float4*)&bias[v * 128 + lane * 4];
        float4 o = make_float4(acc[v].x + bb.x, acc[v].y + bb.y, acc[v].z + bb.z, acc[v].w + bb.w);
        if (relu) {
            o.x = fmaxf(o.x, 0.f); o.y = fmaxf(o.y, 0.f);
            o.z = fmaxf(o.z, 0.f); o.w = fmaxf(o.w, 0.f);
        }
        *(float4*)&out[(size_t)w * D + v * 128 + lane * 4] = o;
    }
}

// ====== layer2 mu: aggregation + bias, then PROJECT row onto dw1_u -> pu ======
// zu2 row (512 wide) lives in warp registers; never written to gmem.
// pu[w, j] = sum_d zu2[w,d] * Wu[d, j],  Wu = dw1[0:512, 0:16]
__global__ void gat_aggr_mu_pu_k(const int* __restrict__ rowptr, const int* __restrict__ csr,
                                 const float* __restrict__ es, const float* __restrict__ ed,
                                 const float* __restrict__ feat, const float* __restrict__ bias,
                                 const float* __restrict__ Wu, float* __restrict__ pu, int nd) {
    __shared__ float Ws[512 * 16];  // 32 KB
    for (int i = threadIdx.x; i < 512 * 16 / 4; i += blockDim.x)
        ((float4*)Ws)[i] = ((const float4*)Wu)[i];
    __syncthreads();
    int w = (blockIdx.x * blockDim.x + threadIdx.x) >> 5;
    int lane = threadIdx.x & 31;
    if (w >= nd) return;
    int rs = rowptr[w], re = rowptr[w + 1];
    float edv[4], m[4], ssum[4];
#pragma unroll
    for (int h = 0; h < 4; h++) { edv[h] = ed[(size_t)w * 4 + h]; m[h] = -INFINITY; ssum[h] = 0.f; }
    for (int i = rs + lane; i < re; i += 32) {
        int s = csr[i];
        float4 ev = *(const float4*)&es[(size_t)s * 4];
        float e4[4] = { ev.x, ev.y, ev.z, ev.w };
#pragma unroll
        for (int h = 0; h < 4; h++) {
            float e = e4[h] + edv[h];
            e = e > 0.f ? e : 0.2f * e;
            m[h] = fmaxf(m[h], e);
        }
    }
#pragma unroll
    for (int h = 0; h < 4; h++)
#pragma unroll
        for (int o = 16; o; o >>= 1) m[h] = fmaxf(m[h], __shfl_xor_sync(0xffffffffu, m[h], o));
    for (int i = rs + lane; i < re; i += 32) {
        int s = csr[i];
        float4 ev = *(const float4*)&es[(size_t)s * 4];
        float e4[4] = { ev.x, ev.y, ev.z, ev.w };
#pragma unroll
        for (int h = 0; h < 4; h++) {
            float e = e4[h] + edv[h];
            e = e > 0.f ? e : 0.2f * e;
            ssum[h] += __expf(e - m[h]);
        }
    }
#pragma unroll
    for (int h = 0; h < 4; h++) {
#pragma unroll
        for (int o = 16; o; o >>= 1) ssum[h] += __shfl_xor_sync(0xffffffffu, ssum[h], o);
        ssum[h] = 1.f / (ssum[h] + 1e-16f);
    }
    float4 acc[4];
#pragma unroll
    for (int v = 0; v < 4; v++) acc[v] = make_float4(0.f, 0.f, 0.f, 0.f);
#pragma unroll 2
    for (int i = rs; i < re; i++) {
        int s = csr[i];
        float4 ev = *(const float4*)&es[(size_t)s * 4];
        float e4[4] = { ev.x, ev.y, ev.z, ev.w };
#pragma unroll
        for (int v = 0; v < 4; v++) {  // h == v (C=128 spans full 128-block)
            float e = e4[v] + edv[v];
            e = e > 0.f ? e : 0.2f * e;
            float a = __expf(e - m[v]) * ssum[v];
            float4 x = *(const float4*)&feat[(size_t)s * 512 + v * 128 + lane * 4];
            acc[v].x += a * x.x; acc[v].y += a * x.y;
            acc[v].z += a * x.z; acc[v].w += a * x.w;
        }
    }
    // project: this lane owns cols {v*128 + lane*4 + c}
    float p[16] = {};
#pragma unroll
    for (int v = 0; v < 4; v++) {
        float4 bb = *(const float4*)&bias[v * 128 + lane * 4];
        float r[4] = { acc[v].x + bb.x, acc[v].y + bb.y, acc[v].z + bb.z, acc[v].w + bb.w };
#pragma unroll
        for (int c = 0; c < 4; c++) {
            int col = v * 128 + lane * 4 + c;
            const float* wr = &Ws[col * 16];
            float rv = r[c];
#pragma unroll
            for (int q = 0; q < 4; q++) {
                float4 wv = *(const float4*)&wr[q * 4];
                p[q * 4 + 0] += rv * wv.x; p[q * 4 + 1] += rv * wv.y;
                p[q * 4 + 2] += rv * wv.z; p[q * 4 + 3] += rv * wv.w;
            }
        }
    }
#pragma unroll
    for (int j = 0; j < 16; j++)
#pragma unroll
        for (int o = 16; o; o >>= 1) p[j] += __shfl_xor_sync(0xffffffffu, p[j], o);
    if (lane == 0) {
#pragma unroll
        for (int q = 0; q < 4; q++)
            *(float4*)&pu[(size_t)w * 16 + q * 4] =
                make_float4(p[q * 4], p[q * 4 + 1], p[q * 4 + 2], p[q * 4 + 3]);
    }
}

// ====== fused aggregate-first (layer2 um): agg[d, h*128+j] = sum alpha_h x[src,j] ===
__global__ void gat_aggr_pre4_k(const int* __restrict__ rowptr, const int* __restrict__ csr,
                                const float* __restrict__ es, const float* __restrict__ ed,
                                const float* __restrict__ x, float* __restrict__ agg, int nd) {
    int w = (blockIdx.x * blockDim.x + threadIdx.x) >> 5;
    int lane = threadIdx.x & 31;
    if (w >= nd) return;
    int rs = rowptr[w], re = rowptr[w + 1];
    float edv[4], m[4], ssum[4];
#pragma unroll
    for (int h = 0; h < 4; h++) { edv[h] = ed[(size_t)w * 4 + h]; m[h] = -INFINITY; ssum[h] = 0.f; }
    for (int i = rs + lane; i < re; i += 32) {
        int s = csr[i];
        float4 ev = *(const float4*)&es[(size_t)s * 4];
        float e4[4] = { ev.x, ev.y, ev.z, ev.w };
#pragma unroll
        for (int h = 0; h < 4; h++) {
            float e = e4[h] + edv[h];
            e = e > 0.f ? e : 0.2f * e;
            m[h] = fmaxf(m[h], e);
        }
    }
#pragma unroll
    for (int h = 0; h < 4; h++)
#pragma unroll
        for (int o = 16; o; o >>= 1) m[h] = fmaxf(m[h], __shfl_xor_sync(0xffffffffu, m[h], o));
    for (int i = rs + lane; i < re; i += 32) {
        int s = csr[i];
        float4 ev = *(const float4*)&es[(size_t)s * 4];
        float e4[4] = { ev.x, ev.y, ev.z, ev.w };
#pragma unroll
        for (int h = 0; h < 4; h++) {
            float e = e4[h] + edv[h];
            e = e > 0.f ? e : 0.2f * e;
            ssum[h] += __expf(e - m[h]);
        }
    }
#pragma unroll
    for (int h = 0; h < 4; h++) {
#pragma unroll
        for (int o = 16; o; o >>= 1) ssum[h] += __shfl_xor_sync(0xffffffffu, ssum[h], o);
        ssum[h] = 1.f / (ssum[h] + 1e-16f);
    }
    float4 acc[4];
#pragma unroll
    for (int h = 0; h < 4; h++) acc[h] = make_float4(0.f, 0.f, 0.f, 0.f);
#pragma unroll 2
    for (int i = rs; i < re; i++) {
        int s = csr[i];
        float4 ev = *(const float4*)&es[(size_t)s * 4];
        float e4[4] = { ev.x, ev.y, ev.z, ev.w };
        float4 xv = *(const float4*)&x[(size_t)s * 128 + lane * 4];
#pragma unroll
        for (int h = 0; h < 4; h++) {
            float e = e4[h] + edv[h];
            e = e > 0.f ? e : 0.2f * e;
            float a = __expf(e - m[h]) * ssum[h];
            acc[h].x += a * xv.x; acc[h].y += a * xv.y;
            acc[h].z += a * xv.z; acc[h].w += a * xv.w;
        }
    }
#pragma unroll
    for (int h = 0; h < 4; h++)
        *(float4*)&agg[(size_t)w * 512 + h * 128 + lane * 4] = acc[h];
}

// ------------- fp32 SIMT GEMM (128x128 tile, 8x8 micro), optional block-diag ---
// If diag: C[:,col0:+128] = A[:,col0+k](lda) @ B[k, col0:+128](ldb), k in [0,K)
__global__ void sgemm_k(const float* __restrict__ A, int lda,
                        const float* __restrict__ B, int ldb,
                        float* __restrict__ C, int ldc,
                        int M, int K, const float* __restrict__ bias, int relu, int diag) {
    __shared__ float As[8][128];
    __shared__ float Bs[8][128];
    int t  = threadIdx.x;
    int tx = t & 15, ty = t >> 4;
    int row0 = blockIdx.y * 128, col0 = blockIdx.x * 128;
    int kof = diag ? col0 : 0;
    float acc[8][8] = {};
    for (int k0 = 0; k0 < K; k0 += 8) {
        {
            int m = t >> 1, k4 = (t & 1) * 4;
            int r = row0 + m;
            float4 v = make_float4(0.f, 0.f, 0.f, 0.f);
            if (r < M) v = *(const float4*)&A[(size_t)r * lda + kof + k0 + k4];
            As[k4 + 0][m] = v.x; As[k4 + 1][m] = v.y;
            As[k4 + 2][m] = v.z; As[k4 + 3][m] = v.w;
        }
        {
            int kk = t >> 5, n4 = (t & 31) * 4;
            *(float4*)&Bs[kk][n4] = *(const float4*)&B[(size_t)(k0 + kk) * ldb + col0 + n4];
        }
        __syncthreads();
#pragma unroll
        for (int kk = 0; kk < 8; kk++) {
            float a_[8], b_[8];
            *(float4*)&a_[0] = *(const float4*)&As[kk][ty * 8];
            *(float4*)&a_[4] = *(const float4*)&As[kk][ty * 8 + 4];
            *(float4*)&b_[0] = *(const float4*)&Bs[kk][tx * 8];
            *(float4*)&b_[4] = *(const float4*)&Bs[kk][tx * 8 + 4];
#pragma unroll
            for (int i = 0; i < 8; i++)
#pragma unroll
                for (int j = 0; j < 8; j++) acc[i][j] += a_[i] * b_[j];
        }
        __syncthreads();
    }
    float bv[8];
#pragma unroll
    for (int j = 0; j < 8; j++) bv[j] = bias ? bias[col0 + tx * 8 + j] : 0.f;
    for (int i = 0; i < 8; i++) {
        int r = row0 + ty * 8 + i;
        if (r >= M) break;
#pragma unroll
        for (int j4 = 0; j4 < 8; j4 += 4) {
            float4 v = make_float4(acc[i][j4] + bv[j4], acc[i][j4 + 1] + bv[j4 + 1],
                                   acc[i][j4 + 2] + bv[j4 + 2], acc[i][j4 + 3] + bv[j4 + 3]);
            if (relu) {
                v.x = fmaxf(v.x, 0.f); v.y = fmaxf(v.y, 0.f);
                v.z = fmaxf(v.z, 0.f); v.w = fmaxf(v.w, 0.f);
            }
            *(float4*)&C[(size_t)r * ldc + col0 + tx * 8 + j4] = v;
        }
    }
}

// ---------- proj16: y[n, 0:16] = x[n, 0:512] @ W[512,16]  (warp per node) ------
__global__ void proj16_k(const float* __restrict__ x, const float* __restrict__ W,
                         float* __restrict__ y, int n) {
    __shared__ float Ws[512 * 16];
    for (int i = threadIdx.x; i < 512 * 16 / 4; i += blockDim.x)
        ((float4*)Ws)[i] = ((const float4*)W)[i];
    __syncthreads();
    int w = (blockIdx.x * blockDim.x + threadIdx.x) >> 5;
    int lane = threadIdx.x & 31;
    if (w >= n) return;
    const float* row = x + (size_t)w * 512;
    float p[16] = {};
#pragma unroll
    for (int k0 = 0; k0 < 512; k0 += 128) {
        float4 xv = *(const float4*)&row[k0 + lane * 4];
        float xs[4] = { xv.x, xv.y, xv.z, xv.w };
#pragma unroll
        for (int c = 0; c < 4; c++) {
            const float* wr = &Ws[(k0 + lane * 4 + c) * 16];
#pragma unroll
            for (int q = 0; q < 4; q++) {
                float4 wv = *(const float4*)&wr[q * 4];
                p[q * 4 + 0] += xs[c] * wv.x; p[q * 4 + 1] += xs[c] * wv.y;
                p[q * 4 + 2] += xs[c] * wv.z; p[q * 4 + 3] += xs[c] * wv.w;
            }
        }
    }
#pragma unroll
    for (int j = 0; j < 16; j++)
#pragma unroll
        for (int o = 16; o; o >>= 1) p[j] += __shfl_xor_sync(0xffffffffu, p[j], o);
    if (lane == 0) {
#pragma unroll
        for (int q = 0; q < 4; q++)
            *(float4*)&y[(size_t)w * 16 + q * 4] =
                make_float4(p[q * 4], p[q * 4 + 1], p[q * 4 + 2], p[q * 4 + 3]);
    }
}

// ---------- decoder edge kernel: out[e] = relu(pu[lu]+pm[lm]+db1)@dw2 + db2 ----
__global__ void dec_edge_k(const float* __restrict__ pu, const float* __restrict__ pm,
                           const int* __restrict__ lu, const int* __restrict__ lm,
                           const float* __restrict__ db1, const float* __restrict__ dw2,
                           const float* __restrict__ db2, float* __restrict__ out, int M) {
    int e = blockIdx.x * blockDim.x + threadIdx.x;
    if (e >= M) return;
    const float4* a = (const float4*)&pu[(size_t)lu[e] * 16];
    const float4* b = (const float4*)&pm[(size_t)lm[e] * 16];
    float acc = db2[0];
#pragma unroll
    for (int q = 0; q < 4; q++) {
        float4 av = a[q], bv = b[q];
        float4 dv = ((const float4*)db1)[q], wv = ((const float4*)dw2)[q];
        acc += fmaxf(av.x + bv.x + dv.x, 0.f) * wv.x;
        acc += fmaxf(av.y + bv.y + dv.y, 0.f) * wv.y;
        acc += fmaxf(av.z + bv.z + dv.z, 0.f) * wv.z;
        acc += fmaxf(av.w + bv.w + dv.w, 0.f) * wv.w;
    }
    out[e] = acc;
}

// ---------------- launch --------------------------------------------------------
extern "C" void kernel_launch(void* const* d_in, const int* in_sizes, int n_in,
                              void* d_out, int out_size) {
    const float* xu     = (const float*)d_in[0];
    const float* xm     = (const float*)d_in[1];
    const int*   um_src = (const int*)d_in[2];
    const int*   um_dst = (const int*)d_in[3];
    const int*   mu_src = (const int*)d_in[4];
    const int*   mu_dst = (const int*)d_in[5];
    const int*   lab_u  = (const int*)d_in[6];
    const int*   lab_m  = (const int*)d_in[7];
    const float* w1um_s = (const float*)d_in[8];
    const float* w1um_d = (const float*)d_in[9];
    const float* a1um_s = (const float*)d_in[10];
    const float* a1um_d = (const float*)d_in[11];
    const float* b1um   = (const float*)d_in[12];
    const float* w1mu_s = (const float*)d_in[13];
    const float* w1mu_d = (const float*)d_in[14];
    const float* a1mu_s = (const float*)d_in[15];
    const float* a1mu_d = (const float*)d_in[16];
    const float* b1mu   = (const float*)d_in[17];
    const float* w2um_s = (const float*)d_in[18];
    const float* w2um_d = (const float*)d_in[19];
    const float* a2um_s = (const float*)d_in[20];
    const float* a2um_d = (const float*)d_in[21];
    const float* b2um   = (const float*)d_in[22];
    const float* w2mu_s = (const float*)d_in[23];
    const float* w2mu_d = (const float*)d_in[24];
    const float* a2mu_s = (const float*)d_in[25];
    const float* a2mu_d = (const float*)d_in[26];
    const float* b2mu   = (const float*)d_in[27];
    const float* dw1    = (const float*)d_in[28];
    const float* db1    = (const float*)d_in[29];
    const float* dw2    = (const float*)d_in[30];
    const float* db2    = (const float*)d_in[31];
    float* out = (float*)d_out;

    float *hs1um, *hs1mu, *hs2mu, *agg, *zu, *zm, *zm2, *pu, *pm;
    float *su1, *su2, *sm1, *sm2, *wa1, *wa2, *wa3, *wa4;
    int *rp_um, *rp_mu, *csr_um, *csr_mu, *cnt_um, *cnt_mu, *bsum;
    cudaGetSymbolAddress((void**)&hs1um, g_hs1um);
    cudaGetSymbolAddress((void**)&hs1mu, g_hs1mu);
    cudaGetSymbolAddress((void**)&hs2mu, g_hs2mu);
    cudaGetSymbolAddress((void**)&agg,   g_agg);
    cudaGetSymbolAddress((void**)&zu,  g_zu);
    cudaGetSymbolAddress((void**)&zm,  g_zm);
    cudaGetSymbolAddress((void**)&zm2, g_zm2);
    cudaGetSymbolAddress((void**)&pu,  g_pu);
    cudaGetSymbolAddress((void**)&pm,  g_pm);
    cudaGetSymbolAddress((void**)&su1, g_su1);
    cudaGetSymbolAddress((void**)&su2, g_su2);
    cudaGetSymbolAddress((void**)&sm1, g_sm1);
    cudaGetSymbolAddress((void**)&sm2, g_sm2);
    cudaGetSymbolAddress((void**)&wa1, g_wa1);
    cudaGetSymbolAddress((void**)&wa2, g_wa2);
    cudaGetSymbolAddress((void**)&wa3, g_wa3);
    cudaGetSymbolAddress((void**)&wa4, g_wa4);
    cudaGetSymbolAddress((void**)&rp_um, g_rp_um);
    cudaGetSymbolAddress((void**)&rp_mu, g_rp_mu);
    cudaGetSymbolAddress((void**)&csr_um, g_csr_um);
    cudaGetSymbolAddress((void**)&csr_mu, g_csr_mu);
    cudaGetSymbolAddress((void**)&cnt_um, g_cnt_um);
    cudaGetSymbolAddress((void**)&cnt_mu, g_cnt_mu);
    cudaGetSymbolAddress((void**)&bsum, g_bsum);

    const int TB = 256;
    const int nb_um = ceil_div(NM, 1024), nb_mu = ceil_div(NU, 1024);

    // ================= CSR build (both graphs, once) =================
    cudaMemsetAsync(cnt_um, 0, NM * sizeof(int));
    cudaMemsetAsync(cnt_mu, 0, NU * sizeof(int));
    hist2_k<<<ceil_div(E, TB), TB>>>(um_dst, mu_dst, cnt_um, cnt_mu, E);
    blk_reduce_k<<<nb_um, 256>>>(cnt_um, bsum, NM);
    scan_bsum_k<<<1, 32>>>(bsum, nb_um);
    blk_scan_k<<<nb_um, 256>>>(cnt_um, bsum, rp_um, NM, E);
    blk_reduce_k<<<nb_mu, 256>>>(cnt_mu, bsum, NU);
    scan_bsum_k<<<1, 32>>>(bsum, nb_mu);
    blk_scan_k<<<nb_mu, 256>>>(cnt_mu, bsum, rp_mu, NU, E);
    cudaMemsetAsync(cnt_um, 0, NM * sizeof(int));
    cudaMemsetAsync(cnt_mu, 0, NU * sizeof(int));
    scatter2_k<<<ceil_div(E, TB), TB>>>(um_src, um_dst, rp_um, cnt_um, csr_um,
                                        mu_src, mu_dst, rp_mu, cnt_mu, csr_mu, E);

    // ================= layer 1 =================
    fold_k<<<ceil_div(FU * H1, TB), TB>>>(w1um_s, a1um_s, wa1, FU, H1, C1);
    fold_k<<<ceil_div(FU * H1, TB), TB>>>(w1mu_d, a1mu_d, wa2, FU, H1, C1);
    fold_k<<<ceil_div(FM * H1, TB), TB>>>(w1um_d, a1um_d, wa3, FM, H1, C1);
    fold_k<<<ceil_div(FM * H1, TB), TB>>>(w1mu_s, a1mu_s, wa4, FM, H1, C1);
    scores2_k<FU, H1><<<ceil_div(NU, 8), 256>>>(xu, wa1, wa2, su1, su2, NU);
    scores2_k<FM, H1><<<ceil_div(NM, 8), 256>>>(xm, wa3, wa4, sm1, sm2, NM);
    sgemm_k<<<dim3(1, ceil_div(NU, 128)), 256>>>(xu, FU, w1um_s, D1, hs1um, D1, NU, FU, nullptr, 0, 0);
    sgemm_k<<<dim3(1, ceil_div(NM, 128)), 256>>>(xm, FM, w1mu_s, D1, hs1mu, D1, NM, FM, nullptr, 0, 0);
    gat_aggr_k<H1, C1><<<ceil_div(NM, 8), 256>>>(rp_um, csr_um, su1, sm1, hs1um, b1um, zm, NM, 1);
    gat_aggr_k<H1, C1><<<ceil_div(NU, 8), 256>>>(rp_mu, csr_mu, sm2, su2, hs1mu, b1mu, zu, NU, 1);

    // ================= layer 2 =================
    fold_k<<<ceil_div(D1 * H2, TB), TB>>>(w2um_s, a2um_s, wa1, D1, H2, C2);
    fold_k<<<ceil_div(D1 * H2, TB), TB>>>(w2mu_d, a2mu_d, wa2, D1, H2, C2);
    fold_k<<<ceil_div(D1 * H2, TB), TB>>>(w2um_d, a2um_d, wa3, D1, H2, C2);
    fold_k<<<ceil_div(D1 * H2, TB), TB>>>(w2mu_s, a2mu_s, wa4, D1, H2, C2);
    scores2_k<D1, H2><<<ceil_div(NU, 8), 256>>>(zu, wa1, wa2, su1, su2, NU);
    scores2_k<D1, H2><<<ceil_div(NM, 8), 256>>>(zm, wa3, wa4, sm1, sm2, NM);
    // um: aggregate-first over zu, then block-diagonal GEMM + bias -> zm2
    gat_aggr_pre4_k<<<ceil_div(NM, 8), 256>>>(rp_um, csr_um, su1, sm1, zu, agg, NM);
    sgemm_k<<<dim3(4, ceil_div(NM, 128)), 256>>>(agg, D2, w2um_s, D2, zm2, D2, NM, D1, b2um, 0, 1);
    // mu: GEMM-first over zm, then fused aggregation + bias + projection -> pu
    sgemm_k<<<dim3(4, ceil_div(NM, 128)), 256>>>(zm, D1, w2mu_s, D2, hs2mu, D2, NM, D1, nullptr, 0, 0);
    gat_aggr_mu_pu_k<<<ceil_div(NU, 8), 256>>>(rp_mu, csr_mu, sm2, su2, hs2mu, b2mu, dw1, pu, NU);

    // ================= decoder =================
    proj16_k<<<ceil_div(NM, 8), 256>>>(zm2, dw1 + (size_t)D2 * HID, pm, NM);
    dec_edge_k<<<ceil_div(EL, TB), TB>>>(pu, pm, lab_u, lab_m, db1, dw2, db2, out, EL);
}

// round 7
// speedup vs baseline: 2.5497x; 2.5497x over previous
#include <cuda_runtime.h>
#include <math.h>

// ---------------- problem constants ----------------
constexpr int NU = 100000, NM = 20000;
constexpr int FU = 32, FM = 128;
constexpr int H1 = 8, C1 = 16, D1 = 128;   // layer 1
constexpr int H2 = 4, C2 = 128, D2 = 512;  // layer 2
constexpr int E = 250000, EL = 200000;
constexpr int HID = 16;

// ---------------- device scratch (static; no allocs allowed) ----------------
__device__ float g_hs1um[(size_t)NU * D1];
__device__ float g_hs1mu[(size_t)NM * D1];
__device__ float g_zu[(size_t)NU * D1];
__device__ float g_zm[(size_t)NM * D1];
__device__ float g_psu[(size_t)NU * 64];   // zu projected through W2um_s@Wm  (per head)
__device__ float g_psm[(size_t)NM * 64];   // zm projected through W2mu_s@Wu  (per head)
__device__ float g_pu[(size_t)NU * HID];
__device__ float g_pm[(size_t)NM * HID];
__device__ float g_su1[(size_t)NU * H1];
__device__ float g_su2[(size_t)NU * H1];
__device__ float g_sm1[(size_t)NM * H1];
__device__ float g_sm2[(size_t)NM * H1];
__device__ float g_wa1[FM * H1];
__device__ float g_wa2[FM * H1];
__device__ float g_wa3[FM * H1];
__device__ float g_wa4[FM * H1];
__device__ float g_wfum[128 * 64];
__device__ float g_wfmu[128 * 64];
__device__ __align__(16) float g_bc[16];
// CSR
__device__ int g_rp_um[NM + 1];
__device__ int g_rp_mu[NU + 1];
__device__ int g_csr_um[E];
__device__ int g_csr_mu[E];
__device__ int g_cnt_um[NM];
__device__ int g_cnt_mu[NU];
__device__ int g_bsum[256];

static inline int ceil_div(int a, int b) { return (a + b - 1) / b; }

// ================= CSR build =================
__global__ void hist2_k(const int* __restrict__ d1, const int* __restrict__ d2,
                        int* __restrict__ c1, int* __restrict__ c2, int ne) {
    int e = blockIdx.x * blockDim.x + threadIdx.x;
    if (e >= ne) return;
    atomicAdd(&c1[d1[e]], 1);
    atomicAdd(&c2[d2[e]], 1);
}

__global__ void blk_reduce_k(const int* __restrict__ deg, int* __restrict__ bsum, int n) {
    __shared__ int sh[256];
    int b = blockIdx.x, tid = threadIdx.x;
    int base = b * 1024;
    int s = 0;
    for (int i = tid; i < 1024; i += 256) {
        int idx = base + i;
        if (idx < n) s += deg[idx];
    }
    sh[tid] = s; __syncthreads();
    for (int o = 128; o; o >>= 1) { if (tid < o) sh[tid] += sh[tid + o]; __syncthreads(); }
    if (tid == 0) bsum[b] = sh[0];
}

__global__ void scan_bsum_k(int* __restrict__ bsum, int nb) {
    if (threadIdx.x == 0) {
        int acc = 0;
        for (int i = 0; i < nb; i++) { int v = bsum[i]; bsum[i] = acc; acc += v; }
    }
}

__global__ void blk_scan_k(const int* __restrict__ deg, const int* __restrict__ bsum,
                           int* __restrict__ rowptr, int n, int ne) {
    __shared__ int ts[256];
    int b = blockIdx.x, tid = threadIdx.x;
    int base = b * 1024 + tid * 4;
    int v[4]; int loc = 0;
#pragma unroll
    for (int j = 0; j < 4; j++) { int idx = base + j; v[j] = (idx < n) ? deg[idx] : 0; loc += v[j]; }
    ts[tid] = loc; __syncthreads();
    for (int o = 1; o < 256; o <<= 1) {
        int t = (tid >= o) ? ts[tid - o] : 0;
        __syncthreads();
        ts[tid] += t;
        __syncthreads();
    }
    int excl = ts[tid] - loc + bsum[b];
#pragma unroll
    for (int j = 0; j < 4; j++) {
        int idx = base + j;
        if (idx < n) rowptr[idx] = excl;
        excl += v[j];
    }
    if (b == 0 && tid == 0) rowptr[n] = ne;
}

__global__ void scatter2_k(const int* __restrict__ s1, const int* __restrict__ d1,
                           const int* __restrict__ rp1, int* __restrict__ c1, int* __restrict__ o1,
                           const int* __restrict__ s2, const int* __restrict__ d2,
                           const int* __restrict__ rp2, int* __restrict__ c2, int* __restrict__ o2,
                           int ne) {
    int e = blockIdx.x * blockDim.x + threadIdx.x;
    if (e >= ne) return;
    { int d = d1[e]; int p = rp1[d] + atomicAdd(&c1[d], 1); o1[p] = s1[e]; }
    { int d = d2[e]; int p = rp2[d] + atomicAdd(&c2[d], 1); o2[p] = s2[e]; }
}

// ================= fold W @ a -> wa[K,H] =================
__global__ void fold_k(const float* __restrict__ W, const float* __restrict__ a,
                       float* __restrict__ wa, int K, int H, int C) {
    int t = blockIdx.x * blockDim.x + threadIdx.x;
    if (t >= K * H) return;
    int k = t / H, h = t - k * H;
    float s = 0.f;
    for (int c = 0; c < C; c++) s += W[(size_t)k * H * C + h * C + c] * a[h * C + c];
    wa[t] = s;
}

// ====== fold decoder weights: Wf[k, h*16+j] = sum_c Ws[k,h*128+c]*dw1[(off+h*128+c)*16+j]
__global__ void fold_dec_k(const float* __restrict__ Ws, const float* __restrict__ dw1,
                           int dec_off, float* __restrict__ Wf) {
    int t = blockIdx.x * blockDim.x + threadIdx.x;
    if (t >= 128 * 64) return;
    int k = t >> 6, hj = t & 63;
    int h = hj >> 4, j = hj & 15;
    const float* wrow = Ws + (size_t)k * 512 + h * 128;
    const float* drow = dw1 + (size_t)(dec_off + h * 128) * 16 + j;
    float s = 0.f;
    for (int c = 0; c < 128; c++) s += wrow[c] * drow[c * 16];
    Wf[t] = s;
}

// ====== bias constant: bc[j] = db1[j] + b2mu@Wu + b2um@Wm ======
__global__ void bias_const_k(const float* __restrict__ b2mu, const float* __restrict__ b2um,
                             const float* __restrict__ dw1, const float* __restrict__ db1,
                             float* __restrict__ bc) {
    int j = threadIdx.x;
    if (j >= 16) return;
    float s = db1[j];
    for (int d = 0; d < 512; d++)
        s += b2mu[d] * dw1[d * 16 + j] + b2um[d] * dw1[(512 + d) * 16 + j];
    bc[j] = s;
}

// ====== scores: read x once, produce y1 = x@wa1, y2 = x@wa2 (warp per node) =====
template <int K, int H>
__global__ void scores2_k(const float* __restrict__ x,
                          const float* __restrict__ wa1, const float* __restrict__ wa2,
                          float* __restrict__ y1, float* __restrict__ y2, int n) {
    __shared__ float s1[K * H], s2[K * H];
    int t = threadIdx.x;
    for (int i = t; i < K * H; i += blockDim.x) { s1[i] = wa1[i]; s2[i] = wa2[i]; }
    __syncthreads();
    int warp = t >> 5, lane = t & 31;
    int node = blockIdx.x * (blockDim.x >> 5) + warp;
    if (node >= n) return;
    const float* row = x + (size_t)node * K;
    float a1[H] = {}, a2[H] = {};
#pragma unroll
    for (int k0 = 0; k0 < K; k0 += 32) {
        float xv = row[k0 + lane];
#pragma unroll
        for (int h = 0; h < H; h++) {
            a1[h] += xv * s1[(k0 + lane) * H + h];
            a2[h] += xv * s2[(k0 + lane) * H + h];
        }
    }
#pragma unroll
    for (int h = 0; h < H; h++) {
#pragma unroll
        for (int o = 16; o; o >>= 1) {
            a1[h] += __shfl_xor_sync(0xffffffffu, a1[h], o);
            a2[h] += __shfl_xor_sync(0xffffffffu, a2[h], o);
        }
    }
    if (lane == 0) {
#pragma unroll
        for (int h = 0; h < H; h++) {
            y1[(size_t)node * H + h] = a1[h];
            y2[(size_t)node * H + h] = a2[h];
        }
    }
}

// ====== fused GAT aggregation (layer1, GEMM-first): warp per dst, no atomics ======
template <int H, int C>
__global__ void gat_aggr_k(const int* __restrict__ rowptr, const int* __restrict__ csr,
                           const float* __restrict__ es, const float* __restrict__ ed,
                           const float* __restrict__ feat, const float* __restrict__ bias,
                           float* __restrict__ out, int nd, int relu) {
    constexpr int D = H * C;
    constexpr int NV = D / 128;
    int w = (blockIdx.x * blockDim.x + threadIdx.x) >> 5;
    int lane = threadIdx.x & 31;
    if (w >= nd) return;
    int rs = rowptr[w], re = rowptr[w + 1];
    float edv[H], m[H], ssum[H];
#pragma unroll
    for (int h = 0; h < H; h++) { edv[h] = ed[(size_t)w * H + h]; m[h] = -INFINITY; ssum[h] = 0.f; }
    for (int i = rs + lane; i < re; i += 32) {
        int s = csr[i];
#pragma unroll
        for (int h = 0; h < H; h++) {
            float e = es[(size_t)s * H + h] + edv[h];
            e = e > 0.f ? e : 0.2f * e;
            m[h] = fmaxf(m[h], e);
        }
    }
#pragma unroll
    for (int h = 0; h < H; h++)
#pragma unroll
        for (int o = 16; o; o >>= 1) m[h] = fmaxf(m[h], __shfl_xor_sync(0xffffffffu, m[h], o));
    for (int i = rs + lane; i < re; i += 32) {
        int s = csr[i];
#pragma unroll
        for (int h = 0; h < H; h++) {
            float e = es[(size_t)s * H + h] + edv[h];
            e = e > 0.f ? e : 0.2f * e;
            ssum[h] += __expf(e - m[h]);
        }
    }
#pragma unroll
    for (int h = 0; h < H; h++) {
#pragma unroll
        for (int o = 16; o; o >>= 1) ssum[h] += __shfl_xor_sync(0xffffffffu, ssum[h], o);
        ssum[h] = 1.f / (ssum[h] + 1e-16f);
    }
    float4 acc[NV];
#pragma unroll
    for (int v = 0; v < NV; v++) acc[v] = make_float4(0.f, 0.f, 0.f, 0.f);
#pragma unroll 2
    for (int i = rs; i < re; i++) {
        int s = csr[i];
#pragma unroll
        for (int v = 0; v < NV; v++) {
            int h = (v * 128 + lane * 4) / C;
            float e = es[(size_t)s * H + h] + edv[h];
            e = e > 0.f ? e : 0.2f * e;
            float a = __expf(e - m[h]) * ssum[h];
            float4 x = *(const float4*)&feat[(size_t)s * D + v * 128 + lane * 4];
            acc[v].x += a * x.x; acc[v].y += a * x.y;
            acc[v].z += a * x.z; acc[v].w += a * x.w;
        }
    }
#pragma unroll
    for (int v = 0; v < NV; v++) {
        float4 bb = *(const float4*)&bias[v * 128 + lane * 4];
        float4 o = make_float4(acc[v].x + bb.x, acc[v].y + bb.y, acc[v].z + bb.z, acc[v].w + bb.w);
        if (relu) {
            o.x = fmaxf(o.x, 0.f); o.y = fmaxf(o.y, 0.f);
            o.z = fmaxf(o.z, 0.f); o.w = fmaxf(o.w, 0.f);
        }
        *(float4*)&out[(size_t)w * D + v * 128 + lane * 4] = o;
    }
}

// ====== layer2: aggregate 64-wide projected features, fold heads -> 16 ======
// out[d, j] = sum_h sum_e alpha_{e,h} * ps[src_e, h*16+j]
__global__ void gat_aggr16_k(const int* __restrict__ rowptr, const int* __restrict__ csr,
                             const float* __restrict__ es, const float* __restrict__ ed,
                             const float* __restrict__ ps, float* __restrict__ out, int nd) {
    int w = (blockIdx.x * blockDim.x + threadIdx.x) >> 5;
    int lane = threadIdx.x & 31;
    if (w >= nd) return;
    int rs = rowptr[w], re = rowptr[w + 1];
    float edv[4], m[4], ssum[4];
#pragma unroll
    for (int h = 0; h < 4; h++) { edv[h] = ed[(size_t)w * 4 + h]; m[h] = -INFINITY; ssum[h] = 0.f; }
    for (int i = rs + lane; i < re; i += 32) {
        int s = csr[i];
        float4 ev = *(const float4*)&es[(size_t)s * 4];
        float e4[4] = { ev.x, ev.y, ev.z, ev.w };
#pragma unroll
        for (int h = 0; h < 4; h++) {
            float e = e4[h] + edv[h];
            e = e > 0.f ? e : 0.2f * e;
            m[h] = fmaxf(m[h], e);
        }
    }
#pragma unroll
    for (int h = 0; h < 4; h++)
#pragma unroll
        for (int o = 16; o; o >>= 1) m[h] = fmaxf(m[h], __shfl_xor_sync(0xffffffffu, m[h], o));
    for (int i = rs + lane; i < re; i += 32) {
        int s = csr[i];
        float4 ev = *(const float4*)&es[(size_t)s * 4];
        float e4[4] = { ev.x, ev.y, ev.z, ev.w };
#pragma unroll
        for (int h = 0; h < 4; h++) {
            float e = e4[h] + edv[h];
            e = e > 0.f ? e : 0.2f * e;
            ssum[h] += __expf(e - m[h]);
        }
    }
#pragma unroll
    for (int h = 0; h < 4; h++) {
#pragma unroll
        for (int o = 16; o; o >>= 1) ssum[h] += __shfl_xor_sync(0xffffffffu, ssum[h], o);
        ssum[h] = 1.f / (ssum[h] + 1e-16f);
    }
    // lane owns cols (2*lane, 2*lane+1) of the 64-wide row; head h = lane>>3
    int hh = lane >> 3;
    float edh = edv[hh], mh = m[hh], sinv = ssum[hh];
    float ax = 0.f, ay = 0.f;
    for (int i = rs; i < re; i++) {
        int s = csr[i];
        float e = es[(size_t)s * 4 + hh] + edh;
        e = e > 0.f ? e : 0.2f * e;
        float a = __expf(e - mh) * sinv;
        float2 v = *(const float2*)&ps[(size_t)s * 64 + lane * 2];
        ax += a * v.x; ay += a * v.y;
    }
    // sum across heads: lanes l, l+8, l+16, l+24 hold same local cols of heads 0..3
    ax += __shfl_xor_sync(0xffffffffu, ax, 8);
    ay += __shfl_xor_sync(0xffffffffu, ay, 8);
    ax += __shfl_xor_sync(0xffffffffu, ax, 16);
    ay += __shfl_xor_sync(0xffffffffu, ay, 16);
    if (lane < 8) *(float2*)&out[(size_t)w * 16 + lane * 2] = make_float2(ax, ay);
}

// ------------- fp32 SIMT GEMM (128x128 tile, 8x8 micro) — layer 1 only --------
__global__ void sgemm_k(const float* __restrict__ A, int lda,
                        const float* __restrict__ B, int ldb,
                        float* __restrict__ C, int ldc,
                        int M, int K) {
    __shared__ float As[8][128];
    __shared__ float Bs[8][128];
    int t  = threadIdx.x;
    int tx = t & 15, ty = t >> 4;
    int row0 = blockIdx.y * 128, col0 = blockIdx.x * 128;
    float acc[8][8] = {};
    for (int k0 = 0; k0 < K; k0 += 8) {
        {
            int m = t >> 1, k4 = (t & 1) * 4;
            int r = row0 + m;
            float4 v = make_float4(0.f, 0.f, 0.f, 0.f);
            if (r < M) v = *(const float4*)&A[(size_t)r * lda + k0 + k4];
            As[k4 + 0][m] = v.x; As[k4 + 1][m] = v.y;
            As[k4 + 2][m] = v.z; As[k4 + 3][m] = v.w;
        }
        {
            int kk = t >> 5, n4 = (t & 31) * 4;
            *(float4*)&Bs[kk][n4] = *(const float4*)&B[(size_t)(k0 + kk) * ldb + col0 + n4];
        }
        __syncthreads();
#pragma unroll
        for (int kk = 0; kk < 8; kk++) {
            float a_[8], b_[8];
            *(float4*)&a_[0] = *(const float4*)&As[kk][ty * 8];
            *(float4*)&a_[4] = *(const float4*)&As[kk][ty * 8 + 4];
            *(float4*)&b_[0] = *(const float4*)&Bs[kk][tx * 8];
            *(float4*)&b_[4] = *(const float4*)&Bs[kk][tx * 8 + 4];
#pragma unroll
            for (int i = 0; i < 8; i++)
#pragma unroll
                for (int j = 0; j < 8; j++) acc[i][j] += a_[i] * b_[j];
        }
        __syncthreads();
    }
    for (int i = 0; i < 8; i++) {
        int r = row0 + ty * 8 + i;
        if (r >= M) break;
#pragma unroll
        for (int j4 = 0; j4 < 8; j4 += 4) {
            float4 v = make_float4(acc[i][j4], acc[i][j4 + 1], acc[i][j4 + 2], acc[i][j4 + 3]);
            *(float4*)&C[(size_t)r * ldc + col0 + tx * 8 + j4] = v;
        }
    }
}

// ---------- proj64: Y[M,64] = X[M,128] @ Wf[128,64]  (tiled GEMM) -------------
// As padded to 132 (multiple of 4) so float4 reads of As rows stay 16B-aligned.
__global__ void proj64_k(const float* __restrict__ X, const float* __restrict__ Wf,
                         float* __restrict__ Y, int M) {
    __shared__ float As[16][132];
    __shared__ float Bs[16][64];
    int t = threadIdx.x;
    int tx = t & 15, ty = t >> 4;
    int row0 = blockIdx.x * 128;
    float acc[8][4] = {};
    for (int k0 = 0; k0 < 128; k0 += 16) {
#pragma unroll
        for (int l = 0; l < 2; l++) {
            int i = t * 2 + l;          // 0..511
            int row = i >> 2, k4 = (i & 3) * 4;
            int r = row0 + row;
            float4 v = make_float4(0.f, 0.f, 0.f, 0.f);
            if (r < M) v = *(const float4*)&X[(size_t)r * 128 + k0 + k4];
            As[k4 + 0][row] = v.x; As[k4 + 1][row] = v.y;
            As[k4 + 2][row] = v.z; As[k4 + 3][row] = v.w;
        }
        {
            int kk = t >> 4, c4 = (t & 15) * 4;
            *(float4*)&Bs[kk][c4] = *(const float4*)&Wf[(size_t)(k0 + kk) * 64 + c4];
        }
        __syncthreads();
#pragma unroll
        for (int kk = 0; kk < 16; kk++) {
            float a_[8], b_[4];
            *(float4*)&a_[0] = *(const float4*)&As[kk][ty * 8];
            *(float4*)&a_[4] = *(const float4*)&As[kk][ty * 8 + 4];
            *(float4*)&b_[0] = *(const float4*)&Bs[kk][tx * 4];
#pragma unroll
            for (int i = 0; i < 8; i++)
#pragma unroll
                for (int j = 0; j < 4; j++) acc[i][j] += a_[i] * b_[j];
        }
        __syncthreads();
    }
    for (int i = 0; i < 8; i++) {
        int r = row0 + ty * 8 + i;
        if (r >= M) break;
        *(float4*)&Y[(size_t)r * 64 + tx * 4] =
            make_float4(acc[i][0], acc[i][1], acc[i][2], acc[i][3]);
    }
}

// ---------- decoder edge kernel: out[e] = relu(pu[lu]+pm[lm]+bc)@dw2 + db2 ----
__global__ void dec_edge_k(const float* __restrict__ pu, const float* __restrict__ pm,
                           const int* __restrict__ lu, const int* __restrict__ lm,
                           const float* __restrict__ bc, const float* __restrict__ dw2,
                           const float* __restrict__ db2, float* __restrict__ out, int M) {
    int e = blockIdx.x * blockDim.x + threadIdx.x;
    if (e >= M) return;
    const float4* a = (const float4*)&pu[(size_t)lu[e] * 16];
    const float4* b = (const float4*)&pm[(size_t)lm[e] * 16];
    float acc = db2[0];
#pragma unroll
    for (int q = 0; q < 4; q++) {
        float4 av = a[q], bv = b[q];
        float4 dv = ((const float4*)bc)[q], wv = ((const float4*)dw2)[q];
        acc += fmaxf(av.x + bv.x + dv.x, 0.f) * wv.x;
        acc += fmaxf(av.y + bv.y + dv.y, 0.f) * wv.y;
        acc += fmaxf(av.z + bv.z + dv.z, 0.f) * wv.z;
        acc += fmaxf(av.w + bv.w + dv.w, 0.f) * wv.w;
    }
    out[e] = acc;
}

// ---------------- launch --------------------------------------------------------
extern "C" void kernel_launch(void* const* d_in, const int* in_sizes, int n_in,
                              void* d_out, int out_size) {
    const float* xu     = (const float*)d_in[0];
    const float* xm     = (const float*)d_in[1];
    const int*   um_src = (const int*)d_in[2];
    const int*   um_dst = (const int*)d_in[3];
    const int*   mu_src = (const int*)d_in[4];
    const int*   mu_dst = (const int*)d_in[5];
    const int*   lab_u  = (const int*)d_in[6];
    const int*   lab_m  = (const int*)d_in[7];
    const float* w1um_s = (const float*)d_in[8];
    const float* w1um_d = (const float*)d_in[9];
    const float* a1um_s = (const float*)d_in[10];
    const float* a1um_d = (const float*)d_in[11];
    const float* b1um   = (const float*)d_in[12];
    const float* w1mu_s = (const float*)d_in[13];
    const float* w1mu_d = (const float*)d_in[14];
    const float* a1mu_s = (const float*)d_in[15];
    const float* a1mu_d = (const float*)d_in[16];
    const float* b1mu   = (const float*)d_in[17];
    const float* w2um_s = (const float*)d_in[18];
    const float* w2um_d = (const float*)d_in[19];
    const float* a2um_s = (const float*)d_in[20];
    const float* a2um_d = (const float*)d_in[21];
    const float* b2um   = (const float*)d_in[22];
    const float* w2mu_s = (const float*)d_in[23];
    const float* w2mu_d = (const float*)d_in[24];
    const float* a2mu_s = (const float*)d_in[25];
    const float* a2mu_d = (const float*)d_in[26];
    const float* b2mu   = (const float*)d_in[27];
    const float* dw1    = (const float*)d_in[28];
    const float* db1    = (const float*)d_in[29];
    const float* dw2    = (const float*)d_in[30];
    const float* db2    = (const float*)d_in[31];
    float* out = (float*)d_out;

    float *hs1um, *hs1mu, *zu, *zm, *psu, *psm, *pu, *pm;
    float *su1, *su2, *sm1, *sm2, *wa1, *wa2, *wa3, *wa4, *wfum, *wfmu, *bc;
    int *rp_um, *rp_mu, *csr_um, *csr_mu, *cnt_um, *cnt_mu, *bsum;
    cudaGetSymbolAddress((void**)&hs1um, g_hs1um);
    cudaGetSymbolAddress((void**)&hs1mu, g_hs1mu);
    cudaGetSymbolAddress((void**)&zu,  g_zu);
    cudaGetSymbolAddress((void**)&zm,  g_zm);
    cudaGetSymbolAddress((void**)&psu, g_psu);
    cudaGetSymbolAddress((void**)&psm, g_psm);
    cudaGetSymbolAddress((void**)&pu,  g_pu);
    cudaGetSymbolAddress((void**)&pm,  g_pm);
    cudaGetSymbolAddress((void**)&su1, g_su1);
    cudaGetSymbolAddress((void**)&su2, g_su2);
    cudaGetSymbolAddress((void**)&sm1, g_sm1);
    cudaGetSymbolAddress((void**)&sm2, g_sm2);
    cudaGetSymbolAddress((void**)&wa1, g_wa1);
    cudaGetSymbolAddress((void**)&wa2, g_wa2);
    cudaGetSymbolAddress((void**)&wa3, g_wa3);
    cudaGetSymbolAddress((void**)&wa4, g_wa4);
    cudaGetSymbolAddress((void**)&wfum, g_wfum);
    cudaGetSymbolAddress((void**)&wfmu, g_wfmu);
    cudaGetSymbolAddress((void**)&bc,  g_bc);
    cudaGetSymbolAddress((void**)&rp_um, g_rp_um);
    cudaGetSymbolAddress((void**)&rp_mu, g_rp_mu);
    cudaGetSymbolAddress((void**)&csr_um, g_csr_um);
    cudaGetSymbolAddress((void**)&csr_mu, g_csr_mu);
    cudaGetSymbolAddress((void**)&cnt_um, g_cnt_um);
    cudaGetSymbolAddress((void**)&cnt_mu, g_cnt_mu);
    cudaGetSymbolAddress((void**)&bsum, g_bsum);

    const int TB = 256;
    const int nb_um = ceil_div(NM, 1024), nb_mu = ceil_div(NU, 1024);

    // ================= CSR build (both graphs, once) =================
    cudaMemsetAsync(cnt_um, 0, NM * sizeof(int));
    cudaMemsetAsync(cnt_mu, 0, NU * sizeof(int));
    hist2_k<<<ceil_div(E, TB), TB>>>(um_dst, mu_dst, cnt_um, cnt_mu, E);
    blk_reduce_k<<<nb_um, 256>>>(cnt_um, bsum, NM);
    scan_bsum_k<<<1, 32>>>(bsum, nb_um);
    blk_scan_k<<<nb_um, 256>>>(cnt_um, bsum, rp_um, NM, E);
    blk_reduce_k<<<nb_mu, 256>>>(cnt_mu, bsum, NU);
    scan_bsum_k<<<1, 32>>>(bsum, nb_mu);
    blk_scan_k<<<nb_mu, 256>>>(cnt_mu, bsum, rp_mu, NU, E);
    cudaMemsetAsync(cnt_um, 0, NM * sizeof(int));
    cudaMemsetAsync(cnt_mu, 0, NU * sizeof(int));
    scatter2_k<<<ceil_div(E, TB), TB>>>(um_src, um_dst, rp_um, cnt_um, csr_um,
                                        mu_src, mu_dst, rp_mu, cnt_mu, csr_mu, E);

    // ================= layer 1 =================
    fold_k<<<ceil_div(FU * H1, TB), TB>>>(w1um_s, a1um_s, wa1, FU, H1, C1);
    fold_k<<<ceil_div(FU * H1, TB), TB>>>(w1mu_d, a1mu_d, wa2, FU, H1, C1);
    fold_k<<<ceil_div(FM * H1, TB), TB>>>(w1um_d, a1um_d, wa3, FM, H1, C1);
    fold_k<<<ceil_div(FM * H1, TB), TB>>>(w1mu_s, a1mu_s, wa4, FM, H1, C1);
    scores2_k<FU, H1><<<ceil_div(NU, 8), 256>>>(xu, wa1, wa2, su1, su2, NU);
    scores2_k<FM, H1><<<ceil_div(NM, 8), 256>>>(xm, wa3, wa4, sm1, sm2, NM);
    sgemm_k<<<dim3(1, ceil_div(NU, 128)), 256>>>(xu, FU, w1um_s, D1, hs1um, D1, NU, FU);
    sgemm_k<<<dim3(1, ceil_div(NM, 128)), 256>>>(xm, FM, w1mu_s, D1, hs1mu, D1, NM, FM);
    gat_aggr_k<H1, C1><<<ceil_div(NM, 8), 256>>>(rp_um, csr_um, su1, sm1, hs1um, b1um, zm, NM, 1);
    gat_aggr_k<H1, C1><<<ceil_div(NU, 8), 256>>>(rp_mu, csr_mu, sm2, su2, hs1mu, b1mu, zu, NU, 1);

    // ================= layer 2 (fully projected to decoder space) =================
    fold_k<<<ceil_div(D1 * H2, TB), TB>>>(w2um_s, a2um_s, wa1, D1, H2, C2);
    fold_k<<<ceil_div(D1 * H2, TB), TB>>>(w2mu_d, a2mu_d, wa2, D1, H2, C2);
    fold_k<<<ceil_div(D1 * H2, TB), TB>>>(w2um_d, a2um_d, wa3, D1, H2, C2);
    fold_k<<<ceil_div(D1 * H2, TB), TB>>>(w2mu_s, a2mu_s, wa4, D1, H2, C2);
    scores2_k<D1, H2><<<ceil_div(NU, 8), 256>>>(zu, wa1, wa2, su1, su2, NU);
    scores2_k<D1, H2><<<ceil_div(NM, 8), 256>>>(zm, wa3, wa4, sm1, sm2, NM);
    // decoder-projected weights + bias constant
    fold_dec_k<<<ceil_div(128 * 64, TB), TB>>>(w2um_s, dw1, 512, wfum);  // movie half
    fold_dec_k<<<ceil_div(128 * 64, TB), TB>>>(w2mu_s, dw1, 0,   wfmu);  // user half
    bias_const_k<<<1, 16>>>(b2mu, b2um, dw1, db1, bc);
    // project node features into (head x 16) decoder space
    proj64_k<<<ceil_div(NU, 128), 256>>>(zu, wfum, psu, NU);
    proj64_k<<<ceil_div(NM, 128), 256>>>(zm, wfmu, psm, NM);
    // aggregate: pm over movies (src users), pu over users (src movies)
    gat_aggr16_k<<<ceil_div(NM, 8), 256>>>(rp_um, csr_um, su1, sm1, psu, pm, NM);
    gat_aggr16_k<<<ceil_div(NU, 8), 256>>>(rp_mu, csr_mu, sm2, su2, psm, pu, NU);

    // ================= decoder =================
    dec_edge_k<<<ceil_div(EL, TB), TB>>>(pu, pm, lab_u, lab_m, bc, dw2, db2, out, EL);
}

// round 9
// speedup vs baseline: 3.5234x; 1.3819x over previous
#include <cuda_runtime.h>
#include <math.h>

// ---------------- problem constants ----------------
constexpr int NU = 100000, NM = 20000;
constexpr int FU = 32, FM = 128;
constexpr int H1 = 8, C1 = 16, D1 = 128;   // layer 1
constexpr int H2 = 4, C2 = 128, D2 = 512;  // layer 2
constexpr int E = 250000, EL = 200000;
constexpr int HID = 16;

// ---------------- device scratch (static; no allocs allowed) ----------------
__device__ float g_agg1[(size_t)NM * 256];   // layer1 um aggregate-first buffer
__device__ float g_hs1mu[(size_t)NM * D1];
__device__ float g_zu[(size_t)NU * D1];
__device__ float g_zm[(size_t)NM * D1];
__device__ float g_psu[(size_t)NU * 64];
__device__ float g_psm[(size_t)NM * 64];
__device__ float g_pu[(size_t)NU * HID];
__device__ float g_pm[(size_t)NM * HID];
__device__ float g_su1[(size_t)NU * H1];
__device__ float g_su2[(size_t)NU * H1];
__device__ float g_sm1[(size_t)NM * H1];
__device__ float g_sm2[(size_t)NM * H1];
__device__ float g_wa1[FU * H1];
__device__ float g_wa2[FU * H1];
__device__ float g_wa3[FM * H1];
__device__ float g_wa4[FM * H1];
__device__ float g_wb1[D1 * H2];
__device__ float g_wb2[D1 * H2];
__device__ float g_wb3[D1 * H2];
__device__ float g_wb4[D1 * H2];
__device__ float g_wfum[128 * 64];
__device__ float g_wfmu[128 * 64];
__device__ __align__(16) float g_bc[16];
// CSR
__device__ int g_rp_um[NM + 1];
__device__ int g_rp_mu[NU + 1];
__device__ int g_csr_um[E];
__device__ int g_csr_mu[E];
__device__ int g_cnt_um[NM];   // degree, then scatter cursor
__device__ int g_cnt_mu[NU];
__device__ int g_bsum[256];    // [0..128) um blocks, [128..256) mu blocks

static inline int ceil_div(int a, int b) { return (a + b - 1) / b; }

// ================= CSR build =================
__global__ void hist2_k(const int* __restrict__ d1, const int* __restrict__ d2,
                        int* __restrict__ c1, int* __restrict__ c2, int ne) {
    int e = blockIdx.x * blockDim.x + threadIdx.x;
    if (e >= ne) return;
    atomicAdd(&c1[d1[e]], 1);
    atomicAdd(&c2[d2[e]], 1);
}

// merged: blocks [0, nb1) reduce deg1, blocks [nb1, nb1+nb2) reduce deg2
__global__ void reduce2_k(const int* __restrict__ deg1, int n1, int nb1,
                          const int* __restrict__ deg2, int n2,
                          int* __restrict__ bsum) {
    __shared__ int sh[256];
    int gb = blockIdx.x, tid = threadIdx.x;
    const int* deg; int n, b, bo;
    if (gb < nb1) { deg = deg1; n = n1; b = gb; bo = 0; }
    else          { deg = deg2; n = n2; b = gb - nb1; bo = 128; }
    int base = b * 1024;
    int s = 0;
    for (int i = tid; i < 1024; i += 256) {
        int idx = base + i;
        if (idx < n) s += deg[idx];
    }
    sh[tid] = s; __syncthreads();
    for (int o = 128; o; o >>= 1) { if (tid < o) sh[tid] += sh[tid + o]; __syncthreads(); }
    if (tid == 0) bsum[bo + b] = sh[0];
}

// thread 0 scans um prefix, thread 32 scans mu prefix
__global__ void scan2_k(int* __restrict__ bsum, int nb1, int nb2) {
    int t = threadIdx.x;
    if (t == 0) {
        int acc = 0;
        for (int i = 0; i < nb1; i++) { int v = bsum[i]; bsum[i] = acc; acc += v; }
    } else if (t == 32) {
        int acc = 0;
        for (int i = 0; i < nb2; i++) { int v = bsum[128 + i]; bsum[128 + i] = acc; acc += v; }
    }
}

// merged block-scan: writes rowptr AND overwrites deg (in place) with the
// exclusive prefix so it doubles as the scatter cursor.
__global__ void blkscan2_k(int* __restrict__ deg1, int* __restrict__ rp1, int n1, int nb1, int ne1,
                           int* __restrict__ deg2, int* __restrict__ rp2, int n2, int ne2,
                           const int* __restrict__ bsum) {
    __shared__ int ts[256];
    int gb = blockIdx.x, tid = threadIdx.x;
    int* deg; int* rp; int n, b, bo, ne;
    if (gb < nb1) { deg = deg1; rp = rp1; n = n1; b = gb; bo = 0; ne = ne1; }
    else          { deg = deg2; rp = rp2; n = n2; b = gb - nb1; bo = 128; ne = ne2; }
    int base = b * 1024 + tid * 4;
    int v[4]; int loc = 0;
#pragma unroll
    for (int j = 0; j < 4; j++) { int idx = base + j; v[j] = (idx < n) ? deg[idx] : 0; loc += v[j]; }
    ts[tid] = loc; __syncthreads();
    for (int o = 1; o < 256; o <<= 1) {
        int t = (tid >= o) ? ts[tid - o] : 0;
        __syncthreads();
        ts[tid] += t;
        __syncthreads();
    }
    int excl = ts[tid] - loc + bsum[bo + b];
#pragma unroll
    for (int j = 0; j < 4; j++) {
        int idx = base + j;
        if (idx < n) { rp[idx] = excl; deg[idx] = excl; }
        excl += v[j];
    }
    if (b == 0 && tid == 0) rp[n] = ne;
}

// scatter via in-place cursor (cur holds absolute positions)
__global__ void scatter2_k(const int* __restrict__ s1, const int* __restrict__ d1,
                           int* __restrict__ cur1, int* __restrict__ o1,
                           const int* __restrict__ s2, const int* __restrict__ d2,
                           int* __restrict__ cur2, int* __restrict__ o2, int ne) {
    int e = blockIdx.x * blockDim.x + threadIdx.x;
    if (e >= ne) return;
    { int p = atomicAdd(&cur1[d1[e]], 1); o1[p] = s1[e]; }
    { int p = atomicAdd(&cur2[d2[e]], 1); o2[p] = s2[e]; }
}

// ================= all weight folds in ONE kernel =================
__device__ __forceinline__ float fold_elem(const float* __restrict__ W,
                                           const float* __restrict__ a,
                                           int H, int C, int t) {
    int k = t / H, h = t - k * H;
    const float* wr = W + (size_t)k * H * C + h * C;
    const float* ar = a + h * C;
    float s = 0.f;
    for (int c = 0; c < C; c++) s += wr[c] * ar[c];
    return s;
}
__device__ __forceinline__ float fold_dec_elem(const float* __restrict__ Ws,
                                               const float* __restrict__ dw1,
                                               int dec_off, int t) {
    int k = t >> 6, hj = t & 63;
    int h = hj >> 4, j = hj & 15;
    const float* wrow = Ws + (size_t)k * 512 + h * 128;
    const float* drow = dw1 + (size_t)(dec_off + h * 128) * 16 + j;
    float s = 0.f;
    for (int c = 0; c < 128; c++) s += wrow[c] * drow[c * 16];
    return s;
}

constexpr int PO1 = 0,            PN1 = FU * H1;     // wa1
constexpr int PO2 = PO1 + PN1,    PN2 = FU * H1;     // wa2
constexpr int PO3 = PO2 + PN2,    PN3 = FM * H1;     // wa3
constexpr int PO4 = PO3 + PN3,    PN4 = FM * H1;     // wa4
constexpr int PO5 = PO4 + PN4,    PN5 = D1 * H2;     // wb1
constexpr int PO6 = PO5 + PN5,    PN6 = D1 * H2;     // wb2
constexpr int PO7 = PO6 + PN6,    PN7 = D1 * H2;     // wb3
constexpr int PO8 = PO7 + PN7,    PN8 = D1 * H2;     // wb4
constexpr int PO9 = PO8 + PN8,    PN9 = 128 * 64;    // wfum
constexpr int PO10 = PO9 + PN9,   PN10 = 128 * 64;   // wfmu
constexpr int PO11 = PO10 + PN10, PN11 = 16;         // bc
constexpr int PTOT = PO11 + PN11;

__global__ void prep_k(const float* w1um_s, const float* a1um_s,
                       const float* w1mu_d, const float* a1mu_d,
                       const float* w1um_d, const float* a1um_d,
                       const float* w1mu_s, const float* a1mu_s,
                       const float* w2um_s, const float* a2um_s,
                       const float* w2mu_d, const float* a2mu_d,
                       const float* w2um_d, const float* a2um_d,
                       const float* w2mu_s, const float* a2mu_s,
                       const float* dw1, const float* db1,
                       const float* b2um, const float* b2mu,
                       float* wa1, float* wa2, float* wa3, float* wa4,
                       float* wb1, float* wb2, float* wb3, float* wb4,
                       float* wfum, float* wfmu, float* bc) {
    int t = blockIdx.x * blockDim.x + threadIdx.x;
    if (t >= PTOT) return;
    if (t < PO2)       wa1[t - PO1] = fold_elem(w1um_s, a1um_s, H1, C1, t - PO1);
    else if (t < PO3)  wa2[t - PO2] = fold_elem(w1mu_d, a1mu_d, H1, C1, t - PO2);
    else if (t < PO4)  wa3[t - PO3] = fold_elem(w1um_d, a1um_d, H1, C1, t - PO3);
    else if (t < PO5)  wa4[t - PO4] = fold_elem(w1mu_s, a1mu_s, H1, C1, t - PO4);
    else if (t < PO6)  wb1[t - PO5] = fold_elem(w2um_s, a2um_s, H2, C2, t - PO5);
    else if (t < PO7)  wb2[t - PO6] = fold_elem(w2mu_d, a2mu_d, H2, C2, t - PO6);
    else if (t < PO8)  wb3[t - PO7] = fold_elem(w2um_d, a2um_d, H2, C2, t - PO7);
    else if (t < PO9)  wb4[t - PO8] = fold_elem(w2mu_s, a2mu_s, H2, C2, t - PO8);
    else if (t < PO10) wfum[t - PO9]  = fold_dec_elem(w2um_s, dw1, 512, t - PO9);
    else if (t < PO11) wfmu[t - PO10] = fold_dec_elem(w2mu_s, dw1, 0,   t - PO10);
    else {
        int j = t - PO11;
        float s = db1[j];
        for (int d = 0; d < 512; d++)
            s += b2mu[d] * dw1[d * 16 + j] + b2um[d] * dw1[(512 + d) * 16 + j];
        bc[j] = s;
    }
}

// ====== scores: read x once, produce y1 = x@wa1, y2 = x@wa2 (warp per node) =====
template <int K, int H>
__global__ void scores2_k(const float* __restrict__ x,
                          const float* __restrict__ wa1, const float* __restrict__ wa2,
                          float* __restrict__ y1, float* __restrict__ y2, int n) {
    __shared__ float s1[K * H], s2[K * H];
    int t = threadIdx.x;
    for (int i = t; i < K * H; i += blockDim.x) { s1[i] = wa1[i]; s2[i] = wa2[i]; }
    __syncthreads();
    int warp = t >> 5, lane = t & 31;
    int node = blockIdx.x * (blockDim.x >> 5) + warp;
    if (node >= n) return;
    const float* row = x + (size_t)node * K;
    float a1[H] = {}, a2[H] = {};
#pragma unroll
    for (int k0 = 0; k0 < K; k0 += 32) {
        float xv = row[k0 + lane];
#pragma unroll
        for (int h = 0; h < H; h++) {
            a1[h] += xv * s1[(k0 + lane) * H + h];
            a2[h] += xv * s2[(k0 + lane) * H + h];
        }
    }
#pragma unroll
    for (int h = 0; h < H; h++) {
#pragma unroll
        for (int o = 16; o; o >>= 1) {
            a1[h] += __shfl_xor_sync(0xffffffffu, a1[h], o);
            a2[h] += __shfl_xor_sync(0xffffffffu, a2[h], o);
        }
    }
    if (lane == 0) {
#pragma unroll
        for (int h = 0; h < H; h++) {
            y1[(size_t)node * H + h] = a1[h];
            y2[(size_t)node * H + h] = a2[h];
        }
    }
}

// ====== layer1 um: aggregate-first over raw xu (FU=32 -> lane=feature) ======
// agg[d, h*32 + lane] = sum_e alpha_{e,h} * xu[src_e, lane]
__global__ void gat_aggr_pre_l1_k(const int* __restrict__ rowptr, const int* __restrict__ csr,
                                  const float* __restrict__ es, const float* __restrict__ ed,
                                  const float* __restrict__ xu, float* __restrict__ agg, int nd) {
    int w = (blockIdx.x * blockDim.x + threadIdx.x) >> 5;
    int lane = threadIdx.x & 31;
    if (w >= nd) return;
    int rs = rowptr[w], re = rowptr[w + 1];
    float edv[8], m[8], ssum[8], acc[8];
    {
        float4 e0 = *(const float4*)&ed[(size_t)w * 8];
        float4 e1 = *(const float4*)&ed[(size_t)w * 8 + 4];
        edv[0]=e0.x; edv[1]=e0.y; edv[2]=e0.z; edv[3]=e0.w;
        edv[4]=e1.x; edv[5]=e1.y; edv[6]=e1.z; edv[7]=e1.w;
    }
#pragma unroll
    for (int h = 0; h < 8; h++) { m[h] = -INFINITY; ssum[h] = 0.f; acc[h] = 0.f; }
    // pass 1: per-head max (lane-strided)
    for (int i = rs + lane; i < re; i += 32) {
        int s = csr[i];
        float4 v0 = *(const float4*)&es[(size_t)s * 8];
        float4 v1 = *(const float4*)&es[(size_t)s * 8 + 4];
        float ev[8] = { v0.x, v0.y, v0.z, v0.w, v1.x, v1.y, v1.z, v1.w };
#pragma unroll
        for (int h = 0; h < 8; h++) {
            float e = ev[h] + edv[h];
            e = e > 0.f ? e : 0.2f * e;
            m[h] = fmaxf(m[h], e);
        }
    }
#pragma unroll
    for (int h = 0; h < 8; h++)
#pragma unroll
        for (int o = 16; o; o >>= 1) m[h] = fmaxf(m[h], __shfl_xor_sync(0xffffffffu, m[h], o));
    // pass 2 (merged expsum + feature): serial over edges
    for (int i = rs; i < re; i++) {
        int s = csr[i];
        float xv = xu[(size_t)s * 32 + lane];
        float4 v0 = *(const float4*)&es[(size_t)s * 8];
        float4 v1 = *(const float4*)&es[(size_t)s * 8 + 4];
        float ev[8] = { v0.x, v0.y, v0.z, v0.w, v1.x, v1.y, v1.z, v1.w };
#pragma unroll
        for (int h = 0; h < 8; h++) {
            float e = ev[h] + edv[h];
            e = e > 0.f ? e : 0.2f * e;
            float a = __expf(e - m[h]);
            ssum[h] += a;
            acc[h] += a * xv;
        }
    }
#pragma unroll
    for (int h = 0; h < 8; h++)
        agg[(size_t)w * 256 + h * 32 + lane] = acc[h] * (1.f / (ssum[h] + 1e-16f));
}

// ====== layer1 um post: zm[d,j] = relu( sum_k agg[d,(j/16)*32+k]*W[k,j] + b[j] )
__global__ void l1post_k(const float* __restrict__ agg, const float* __restrict__ W,
                         const float* __restrict__ b, float* __restrict__ zm, int n) {
    __shared__ float ws[32 * 128];
    __shared__ float bs[128];
    for (int i = threadIdx.x; i < 32 * 128 / 4; i += 256)
        ((float4*)ws)[i] = ((const float4*)W)[i];
    if (threadIdx.x < 32) ((float4*)bs)[threadIdx.x] = ((const float4*)b)[threadIdx.x];
    __syncthreads();
    int j = threadIdx.x & 127;
    int half = threadIdx.x >> 7;
    int h = j >> 4;
    for (int r = blockIdx.x * 2 + half; r < n; r += gridDim.x * 2) {
        const float* arow = agg + (size_t)r * 256 + h * 32;
        float s = bs[j];
#pragma unroll
        for (int k = 0; k < 32; k++) s += arow[k] * ws[k * 128 + j];
        zm[(size_t)r * 128 + j] = fmaxf(s, 0.f);
    }
}

// ====== layer1 mu: fused aggregation (2-pass), D=128, H=8, C=16 ======
__global__ void gat_aggr_l1mu_k(const int* __restrict__ rowptr, const int* __restrict__ csr,
                                const float* __restrict__ es, const float* __restrict__ ed,
                                const float* __restrict__ feat, const float* __restrict__ bias,
                                float* __restrict__ out, int nd) {
    int w = (blockIdx.x * blockDim.x + threadIdx.x) >> 5;
    int lane = threadIdx.x & 31;
    if (w >= nd) return;
    int rs = rowptr[w], re = rowptr[w + 1];
    float edv[8], m[8];
    {
        float4 e0 = *(const float4*)&ed[(size_t)w * 8];
        float4 e1 = *(const float4*)&ed[(size_t)w * 8 + 4];
        edv[0]=e0.x; edv[1]=e0.y; edv[2]=e0.z; edv[3]=e0.w;
        edv[4]=e1.x; edv[5]=e1.y; edv[6]=e1.z; edv[7]=e1.w;
    }
#pragma unroll
    for (int h = 0; h < 8; h++) m[h] = -INFINITY;
    for (int i = rs + lane; i < re; i += 32) {
        int s = csr[i];
        float4 v0 = *(const float4*)&es[(size_t)s * 8];
        float4 v1 = *(const float4*)&es[(size_t)s * 8 + 4];
        float ev[8] = { v0.x, v0.y, v0.z, v0.w, v1.x, v1.y, v1.z, v1.w };
#pragma unroll
        for (int h = 0; h < 8; h++) {
            float e = ev[h] + edv[h];
            e = e > 0.f ? e : 0.2f * e;
            m[h] = fmaxf(m[h], e);
        }
    }
#pragma unroll
    for (int h = 0; h < 8; h++)
#pragma unroll
        for (int o = 16; o; o >>= 1) m[h] = fmaxf(m[h], __shfl_xor_sync(0xffffffffu, m[h], o));
    // merged pass: this lane's head h = lane/4 (covers cols lane*4..+3, C=16)
    int hh = lane >> 2;
    float edh = edv[hh], mh = m[hh];
    float ssum = 0.f;
    float4 acc = make_float4(0.f, 0.f, 0.f, 0.f);
    for (int i = rs; i < re; i++) {
        int s = csr[i];
        float e = es[(size_t)s * 8 + hh] + edh;
        e = e > 0.f ? e : 0.2f * e;
        float a = __expf(e - mh);
        ssum += a;
        float4 x = *(const float4*)&feat[(size_t)s * 128 + lane * 4];
        acc.x += a * x.x; acc.y += a * x.y;
        acc.z += a * x.z; acc.w += a * x.w;
    }
    float sinv = 1.f / (ssum + 1e-16f);
    float4 bb = *(const float4*)&bias[lane * 4];
    float4 o = make_float4(fmaxf(acc.x * sinv + bb.x, 0.f), fmaxf(acc.y * sinv + bb.y, 0.f),
                           fmaxf(acc.z * sinv + bb.z, 0.f), fmaxf(acc.w * sinv + bb.w, 0.f));
    *(float4*)&out[(size_t)w * 128 + lane * 4] = o;
}

// ====== layer2: aggregate 64-wide projected features (2-pass), fold heads -> 16 ==
__global__ void gat_aggr16_k(const int* __restrict__ rowptr, const int* __restrict__ csr,
                             const float* __restrict__ es, const float* __restrict__ ed,
                             const float* __restrict__ ps, float* __restrict__ out, int nd) {
    int w = (blockIdx.x * blockDim.x + threadIdx.x) >> 5;
    int lane = threadIdx.x & 31;
    if (w >= nd) return;
    int rs = rowptr[w], re = rowptr[w + 1];
    float edv[4], m[4];
    {
        float4 e0 = *(const float4*)&ed[(size_t)w * 4];
        edv[0]=e0.x; edv[1]=e0.y; edv[2]=e0.z; edv[3]=e0.w;
    }
#pragma unroll
    for (int h = 0; h < 4; h++) m[h] = -INFINITY;
    for (int i = rs + lane; i < re; i += 32) {
        int s = csr[i];
        float4 ev = *(const float4*)&es[(size_t)s * 4];
        float e4[4] = { ev.x, ev.y, ev.z, ev.w };
#pragma unroll
        for (int h = 0; h < 4; h++) {
            float e = e4[h] + edv[h];
            e = e > 0.f ? e : 0.2f * e;
            m[h] = fmaxf(m[h], e);
        }
    }
#pragma unroll
    for (int h = 0; h < 4; h++)
#pragma unroll
        for (int o = 16; o; o >>= 1) m[h] = fmaxf(m[h], __shfl_xor_sync(0xffffffffu, m[h], o));
    // merged pass: lane owns cols (2*lane, 2*lane+1); head hh = lane>>3
    int hh = lane >> 3;
    float edh = edv[hh], mh = m[hh];
    float ssum = 0.f, ax = 0.f, ay = 0.f;
    for (int i = rs; i < re; i++) {
        int s = csr[i];
        float e = es[(size_t)s * 4 + hh] + edh;
        e = e > 0.f ? e : 0.2f * e;
        float a = __expf(e - mh);
        ssum += a;
        float2 v = *(const float2*)&ps[(size_t)s * 64 + lane * 2];
        ax += a * v.x; ay += a * v.y;
    }
    float sinv = 1.f / (ssum + 1e-16f);
    ax *= sinv; ay *= sinv;
    ax += __shfl_xor_sync(0xffffffffu, ax, 8);
    ay += __shfl_xor_sync(0xffffffffu, ay, 8);
    ax += __shfl_xor_sync(0xffffffffu, ax, 16);
    ay += __shfl_xor_sync(0xffffffffu, ay, 16);
    if (lane < 8) *(float2*)&out[(size_t)w * 16 + lane * 2] = make_float2(ax, ay);
}

// ------------- fp32 SIMT GEMM (128x128 tile, 8x8 micro) — hs1mu only ----------
__global__ void sgemm_k(const float* __restrict__ A, int lda,
                        const float* __restrict__ B, int ldb,
                        float* __restrict__ C, int ldc,
                        int M, int K) {
    __shared__ float As[8][128];
    __shared__ float Bs[8][128];
    int t  = threadIdx.x;
    int tx = t & 15, ty = t >> 4;
    int row0 = blockIdx.y * 128, col0 = blockIdx.x * 128;
    float acc[8][8] = {};
    for (int k0 = 0; k0 < K; k0 += 8) {
        {
            int m = t >> 1, k4 = (t & 1) * 4;
            int r = row0 + m;
            float4 v = make_float4(0.f, 0.f, 0.f, 0.f);
            if (r < M) v = *(const float4*)&A[(size_t)r * lda + k0 + k4];
            As[k4 + 0][m] = v.x; As[k4 + 1][m] = v.y;
            As[k4 + 2][m] = v.z; As[k4 + 3][m] = v.w;
        }
        {
            int kk = t >> 5, n4 = (t & 31) * 4;
            *(float4*)&Bs[kk][n4] = *(const float4*)&B[(size_t)(k0 + kk) * ldb + col0 + n4];
        }
        __syncthreads();
#pragma unroll
        for (int kk = 0; kk < 8; kk++) {
            float a_[8], b_[8];
            *(float4*)&a_[0] = *(const float4*)&As[kk][ty * 8];
            *(float4*)&a_[4] = *(const float4*)&As[kk][ty * 8 + 4];
            *(float4*)&b_[0] = *(const float4*)&Bs[kk][tx * 8];
            *(float4*)&b_[4] = *(const float4*)&Bs[kk][tx * 8 + 4];
#pragma unroll
            for (int i = 0; i < 8; i++)
#pragma unroll
                for (int j = 0; j < 8; j++) acc[i][j] += a_[i] * b_[j];
        }
        __syncthreads();
    }
    for (int i = 0; i < 8; i++) {
        int r = row0 + ty * 8 + i;
        if (r >= M) break;
#pragma unroll
        for (int j4 = 0; j4 < 8; j4 += 4) {
            float4 v = make_float4(acc[i][j4], acc[i][j4 + 1], acc[i][j4 + 2], acc[i][j4 + 3]);
            *(float4*)&C[(size_t)r * ldc + col0 + tx * 8 + j4] = v;
        }
    }
}

// ---------- proj64: Y[M,64] = X[M,128] @ Wf[128,64]  (tiled GEMM) -------------
__global__ void proj64_k(const float* __restrict__ X, const float* __restrict__ Wf,
                         float* __restrict__ Y, int M) {
    __shared__ float As[16][132];
    __shared__ float Bs[16][64];
    int t = threadIdx.x;
    int tx = t & 15, ty = t >> 4;
    int row0 = blockIdx.x * 128;
    float acc[8][4] = {};
    for (int k0 = 0; k0 < 128; k0 += 16) {
#pragma unroll
        for (int l = 0; l < 2; l++) {
            int i = t * 2 + l;
            int row = i >> 2, k4 = (i & 3) * 4;
            int r = row0 + row;
            float4 v = make_float4(0.f, 0.f, 0.f, 0.f);
            if (r < M) v = *(const float4*)&X[(size_t)r * 128 + k0 + k4];
            As[k4 + 0][row] = v.x; As[k4 + 1][row] = v.y;
            As[k4 + 2][row] = v.z; As[k4 + 3][row] = v.w;
        }
        {
            int kk = t >> 4, c4 = (t & 15) * 4;
            *(float4*)&Bs[kk][c4] = *(const float4*)&Wf[(size_t)(k0 + kk) * 64 + c4];
        }
        __syncthreads();
#pragma unroll
        for (int kk = 0; kk < 16; kk++) {
            float a_[8], b_[4];
            *(float4*)&a_[0] = *(const float4*)&As[kk][ty * 8];
            *(float4*)&a_[4] = *(const float4*)&As[kk][ty * 8 + 4];
            *(float4*)&b_[0] = *(const float4*)&Bs[kk][tx * 4];
#pragma unroll
            for (int i = 0; i < 8; i++)
#pragma unroll
                for (int j = 0; j < 4; j++) acc[i][j] += a_[i] * b_[j];
        }
        __syncthreads();
    }
    for (int i = 0; i < 8; i++) {
        int r = row0 + ty * 8 + i;
        if (r >= M) break;
        *(float4*)&Y[(size_t)r * 64 + tx * 4] =
            make_float4(acc[i][0], acc[i][1], acc[i][2], acc[i][3]);
    }
}

// ---------- decoder edge kernel: out[e] = relu(pu[lu]+pm[lm]+bc)@dw2 + db2 ----
__global__ void dec_edge_k(const float* __restrict__ pu, const float* __restrict__ pm,
                           const int* __restrict__ lu, const int* __restrict__ lm,
                           const float* __restrict__ bc, const float* __restrict__ dw2,
                           const float* __restrict__ db2, float* __restrict__ out, int M) {
    int e = blockIdx.x * blockDim.x + threadIdx.x;
    if (e >= M) return;
    const float4* a = (const float4*)&pu[(size_t)lu[e] * 16];
    const float4* b = (const float4*)&pm[(size_t)lm[e] * 16];
    float acc = db2[0];
#pragma unroll
    for (int q = 0; q < 4; q++) {
        float4 av = a[q], bv = b[q];
        float4 dv = ((const float4*)bc)[q], wv = ((const float4*)dw2)[q];
        acc += fmaxf(av.x + bv.x + dv.x, 0.f) * wv.x;
        acc += fmaxf(av.y + bv.y + dv.y, 0.f) * wv.y;
        acc += fmaxf(av.z + bv.z + dv.z, 0.f) * wv.z;
        acc += fmaxf(av.w + bv.w + dv.w, 0.f) * wv.w;
    }
    out[e] = acc;
}

// ---------------- launch --------------------------------------------------------
extern "C" void kernel_launch(void* const* d_in, const int* in_sizes, int n_in,
                              void* d_out, int out_size) {
    const float* xu     = (const float*)d_in[0];
    const float* xm     = (const float*)d_in[1];
    const int*   um_src = (const int*)d_in[2];
    const int*   um_dst = (const int*)d_in[3];
    const int*   mu_src = (const int*)d_in[4];
    const int*   mu_dst = (const int*)d_in[5];
    const int*   lab_u  = (const int*)d_in[6];
    const int*   lab_m  = (const int*)d_in[7];
    const float* w1um_s = (const float*)d_in[8];
    const float* w1um_d = (const float*)d_in[9];
    const float* a1um_s = (const float*)d_in[10];
    const float* a1um_d = (const float*)d_in[11];
    const float* b1um   = (const float*)d_in[12];
    const float* w1mu_s = (const float*)d_in[13];
    const float* w1mu_d = (const float*)d_in[14];
    const float* a1mu_s = (const float*)d_in[15];
    const float* a1mu_d = (const float*)d_in[16];
    const float* b1mu   = (const float*)d_in[17];
    const float* w2um_s = (const float*)d_in[18];
    const float* w2um_d = (const float*)d_in[19];
    const float* a2um_s = (const float*)d_in[20];
    const float* a2um_d = (const float*)d_in[21];
    const float* b2um   = (const float*)d_in[22];
    const float* w2mu_s = (const float*)d_in[23];
    const float* w2mu_d = (const float*)d_in[24];
    const float* a2mu_s = (const float*)d_in[25];
    const float* a2mu_d = (const float*)d_in[26];
    const float* b2mu   = (const float*)d_in[27];
    const float* dw1    = (const float*)d_in[28];
    const float* db1    = (const float*)d_in[29];
    const float* dw2    = (const float*)d_in[30];
    const float* db2    = (const float*)d_in[31];
    float* out = (float*)d_out;

    float *agg1, *hs1mu, *zu, *zm, *psu, *psm, *pu, *pm;
    float *su1, *su2, *sm1, *sm2;
    float *wa1, *wa2, *wa3, *wa4, *wb1, *wb2, *wb3, *wb4, *wfum, *wfmu, *bc;
    int *rp_um, *rp_mu, *csr_um, *csr_mu, *cnt_um, *cnt_mu, *bsum;
    cudaGetSymbolAddress((void**)&agg1,  g_agg1);
    cudaGetSymbolAddress((void**)&hs1mu, g_hs1mu);
    cudaGetSymbolAddress((void**)&zu,  g_zu);
    cudaGetSymbolAddress((void**)&zm,  g_zm);
    cudaGetSymbolAddress((void**)&psu, g_psu);
    cudaGetSymbolAddress((void**)&psm, g_psm);
    cudaGetSymbolAddress((void**)&pu,  g_pu);
    cudaGetSymbolAddress((void**)&pm,  g_pm);
    cudaGetSymbolAddress((void**)&su1, g_su1);
    cudaGetSymbolAddress((void**)&su2, g_su2);
    cudaGetSymbolAddress((void**)&sm1, g_sm1);
    cudaGetSymbolAddress((void**)&sm2, g_sm2);
    cudaGetSymbolAddress((void**)&wa1, g_wa1);
    cudaGetSymbolAddress((void**)&wa2, g_wa2);
    cudaGetSymbolAddress((void**)&wa3, g_wa3);
    cudaGetSymbolAddress((void**)&wa4, g_wa4);
    cudaGetSymbolAddress((void**)&wb1, g_wb1);
    cudaGetSymbolAddress((void**)&wb2, g_wb2);
    cudaGetSymbolAddress((void**)&wb3, g_wb3);
    cudaGetSymbolAddress((void**)&wb4, g_wb4);
    cudaGetSymbolAddress((void**)&wfum, g_wfum);
    cudaGetSymbolAddress((void**)&wfmu, g_wfmu);
    cudaGetSymbolAddress((void**)&bc,  g_bc);
    cudaGetSymbolAddress((void**)&rp_um, g_rp_um);
    cudaGetSymbolAddress((void**)&rp_mu, g_rp_mu);
    cudaGetSymbolAddress((void**)&csr_um, g_csr_um);
    cudaGetSymbolAddress((void**)&csr_mu, g_csr_mu);
    cudaGetSymbolAddress((void**)&cnt_um, g_cnt_um);
    cudaGetSymbolAddress((void**)&cnt_mu, g_cnt_mu);
    cudaGetSymbolAddress((void**)&bsum, g_bsum);

    const int TB = 256;
    const int nb_um = ceil_div(NM, 1024), nb_mu = ceil_div(NU, 1024);

    // ================= CSR build (both graphs, merged stages) =================
    cudaMemsetAsync(cnt_um, 0, NM * sizeof(int));
    cudaMemsetAsync(cnt_mu, 0, NU * sizeof(int));
    hist2_k<<<ceil_div(E, TB), TB>>>(um_dst, mu_dst, cnt_um, cnt_mu, E);
    reduce2_k<<<nb_um + nb_mu, 256>>>(cnt_um, NM, nb_um, cnt_mu, NU, bsum);
    scan2_k<<<1, 64>>>(bsum, nb_um, nb_mu);
    blkscan2_k<<<nb_um + nb_mu, 256>>>(cnt_um, rp_um, NM, nb_um, E, cnt_mu, rp_mu, NU, E, bsum);
    scatter2_k<<<ceil_div(E, TB), TB>>>(um_src, um_dst, cnt_um, csr_um,
                                        mu_src, mu_dst, cnt_mu, csr_mu, E);

    // ================= all weight folds (one launch) =================
    prep_k<<<ceil_div(PTOT, TB), TB>>>(w1um_s, a1um_s, w1mu_d, a1mu_d,
                                       w1um_d, a1um_d, w1mu_s, a1mu_s,
                                       w2um_s, a2um_s, w2mu_d, a2mu_d,
                                       w2um_d, a2um_d, w2mu_s, a2mu_s,
                                       dw1, db1, b2um, b2mu,
                                       wa1, wa2, wa3, wa4, wb1, wb2, wb3, wb4,
                                       wfum, wfmu, bc);

    // ================= layer 1 =================
    scores2_k<FU, H1><<<ceil_div(NU, 8), 256>>>(xu, wa1, wa2, su1, su2, NU);
    scores2_k<FM, H1><<<ceil_div(NM, 8), 256>>>(xm, wa3, wa4, sm1, sm2, NM);
    // um: aggregate-first over xu, then per-head [32->16] GEMM + bias + relu
    gat_aggr_pre_l1_k<<<ceil_div(NM, 8), 256>>>(rp_um, csr_um, su1, sm1, xu, agg1, NM);
    l1post_k<<<1024, 256>>>(agg1, w1um_s, b1um, zm, NM);
    // mu: GEMM-first over xm, then fused 2-pass aggregation + bias + relu
    sgemm_k<<<dim3(1, ceil_div(NM, 128)), 256>>>(xm, FM, w1mu_s, D1, hs1mu, D1, NM, FM);
    gat_aggr_l1mu_k<<<ceil_div(NU, 8), 256>>>(rp_mu, csr_mu, sm2, su2, hs1mu, b1mu, zu, NU);

    // ================= layer 2 (fully projected to decoder space) =================
    scores2_k<D1, H2><<<ceil_div(NU, 8), 256>>>(zu, wb1, wb2, su1, su2, NU);
    scores2_k<D1, H2><<<ceil_div(NM, 8), 256>>>(zm, wb3, wb4, sm1, sm2, NM);
    proj64_k<<<ceil_div(NU, 128), 256>>>(zu, wfum, psu, NU);
    proj64_k<<<ceil_div(NM, 128), 256>>>(zm, wfmu, psm, NM);
    gat_aggr16_k<<<ceil_div(NM, 8), 256>>>(rp_um, csr_um, su1, sm1, psu, pm, NM);
    gat_aggr16_k<<<ceil_div(NU, 8), 256>>>(rp_mu, csr_mu, sm2, su2, psm, pu, NU);

    // ================= decoder =================
    dec_edge_k<<<ceil_div(EL, TB), TB>>>(pu, pm, lab_u, lab_m, bc, dw2, db2, out, EL);
}

// round 11
// speedup vs baseline: 4.0046x; 1.1366x over previous
#include <cuda_runtime.h>
#include <math.h>

// ---------------- problem constants ----------------
constexpr int NU = 100000, NM = 20000;
constexpr int FU = 32, FM = 128;
constexpr int H1 = 8, C1 = 16, D1 = 128;   // layer 1
constexpr int H2 = 4, C2 = 128, D2 = 512;  // layer 2
constexpr int E = 250000, EL = 200000;
constexpr int HID = 16;

// ---------------- device scratch ----------------
__device__ float g_agg1[(size_t)NM * 256];
__device__ float g_hs1mu[(size_t)NM * D1];
__device__ float g_zu[(size_t)NU * D1];
__device__ float g_zm[(size_t)NM * D1];
__device__ float g_psu[(size_t)NU * 64];
__device__ float g_psm[(size_t)NM * 64];
__device__ float g_pu[(size_t)NU * HID];
__device__ float g_pm[(size_t)NM * HID];
__device__ float g_su1[(size_t)NU * H1];
__device__ float g_su2[(size_t)NU * H1];
__device__ float g_sm1[(size_t)NM * H1];
__device__ float g_sm2[(size_t)NM * H1];
__device__ float g_wa1[FU * H1];
__device__ float g_wa2[FU * H1];
__device__ float g_wa3[FM * H1];
__device__ float g_wa4[FM * H1];
__device__ float g_wb1[D1 * H2];
__device__ float g_wb2[D1 * H2];
__device__ float g_wb3[D1 * H2];
__device__ float g_wb4[D1 * H2];
__device__ float g_wfum[128 * 64];
__device__ float g_wfmu[128 * 64];
__device__ __align__(16) float g_bc[16];
// CSR
__device__ int g_rp_um[NM + 1];
__device__ int g_rp_mu[NU + 1];
__device__ int g_csr_um[E];
__device__ int g_csr_mu[E];
__device__ int g_cnt[NM + NU];   // [0,NM) um, [NM,NM+NU) mu; degree then cursor
__device__ int g_bsum[256];

static inline int ceil_div(int a, int b) { return (a + b - 1) / b; }

// ---------------- prep sizing ----------------
constexpr int PO1 = 0,            PN1 = FU * H1;
constexpr int PO2 = PO1 + PN1,    PN2 = FU * H1;
constexpr int PO3 = PO2 + PN2,    PN3 = FM * H1;
constexpr int PO4 = PO3 + PN3,    PN4 = FM * H1;
constexpr int PO5 = PO4 + PN4,    PN5 = D1 * H2;
constexpr int PO6 = PO5 + PN5,    PN6 = D1 * H2;
constexpr int PO7 = PO6 + PN6,    PN7 = D1 * H2;
constexpr int PO8 = PO7 + PN7,    PN8 = D1 * H2;
constexpr int PO9 = PO8 + PN8,    PN9 = 128 * 64;
constexpr int PO10 = PO9 + PN9,   PN10 = 128 * 64;
constexpr int PO11 = PO10 + PN10, PN11 = 16;
constexpr int PTOT = PO11 + PN11;

// ---------------- dispatch block counts ----------------
constexpr int NB_HIST = (E + 255) / 256;
constexpr int NB_PREP = (PTOT + 255) / 256;
constexpr int NB_F1 = NB_HIST + NB_PREP;
constexpr int NB_SXU  = (NU + 7) / 8;
constexpr int NB_SXM  = (NM + 7) / 8;
constexpr int NB_F2 = NB_SXU + NB_SXM;
constexpr int NB_AG_UM = (NM + 7) / 8;
constexpr int NB_AG_MU = (NU + 7) / 8;
constexpr int NB_AGGR = NB_AG_UM + NB_AG_MU;
constexpr int NB_L1POST = 512;
constexpr int NB_PROJU = (NU + 127) / 128;
constexpr int NB_MID = NB_L1POST + NB_PROJU;
constexpr int NB_PROJM = (NM + 127) / 128;

// ================= CSR helpers =================
__global__ void reduce2_k(const int* __restrict__ deg1, int n1, int nb1,
                          const int* __restrict__ deg2, int n2,
                          int* __restrict__ bsum) {
    __shared__ int sh[256];
    int gb = blockIdx.x, tid = threadIdx.x;
    const int* deg; int n, b, bo;
    if (gb < nb1) { deg = deg1; n = n1; b = gb; bo = 0; }
    else          { deg = deg2; n = n2; b = gb - nb1; bo = 128; }
    int base = b * 1024;
    int s = 0;
    for (int i = tid; i < 1024; i += 256) {
        int idx = base + i;
        if (idx < n) s += deg[idx];
    }
    sh[tid] = s; __syncthreads();
    for (int o = 128; o; o >>= 1) { if (tid < o) sh[tid] += sh[tid + o]; __syncthreads(); }
    if (tid == 0) bsum[bo + b] = sh[0];
}

__global__ void scan2_k(int* __restrict__ bsum, int nb1, int nb2) {
    int t = threadIdx.x;
    if (t == 0) {
        int acc = 0;
        for (int i = 0; i < nb1; i++) { int v = bsum[i]; bsum[i] = acc; acc += v; }
    } else if (t == 32) {
        int acc = 0;
        for (int i = 0; i < nb2; i++) { int v = bsum[128 + i]; bsum[128 + i] = acc; acc += v; }
    }
}

__global__ void blkscan2_k(int* __restrict__ deg1, int* __restrict__ rp1, int n1, int nb1, int ne1,
                           int* __restrict__ deg2, int* __restrict__ rp2, int n2, int ne2,
                           const int* __restrict__ bsum) {
    __shared__ int ts[256];
    int gb = blockIdx.x, tid = threadIdx.x;
    int* deg; int* rp; int n, b, bo, ne;
    if (gb < nb1) { deg = deg1; rp = rp1; n = n1; b = gb; bo = 0; ne = ne1; }
    else          { deg = deg2; rp = rp2; n = n2; b = gb - nb1; bo = 128; ne = ne2; }
    int base = b * 1024 + tid * 4;
    int v[4]; int loc = 0;
#pragma unroll
    for (int j = 0; j < 4; j++) { int idx = base + j; v[j] = (idx < n) ? deg[idx] : 0; loc += v[j]; }
    ts[tid] = loc; __syncthreads();
    for (int o = 1; o < 256; o <<= 1) {
        int t = (tid >= o) ? ts[tid - o] : 0;
        __syncthreads();
        ts[tid] += t;
        __syncthreads();
    }
    int excl = ts[tid] - loc + bsum[bo + b];
#pragma unroll
    for (int j = 0; j < 4; j++) {
        int idx = base + j;
        if (idx < n) { rp[idx] = excl; deg[idx] = excl; }
        excl += v[j];
    }
    if (b == 0 && tid == 0) rp[n] = ne;
}

__global__ void scatter2_k(const int* __restrict__ s1, const int* __restrict__ d1,
                           int* __restrict__ cur1, int* __restrict__ o1,
                           const int* __restrict__ s2, const int* __restrict__ d2,
                           int* __restrict__ cur2, int* __restrict__ o2, int ne) {
    int e = blockIdx.x * blockDim.x + threadIdx.x;
    if (e >= ne) return;
    { int p = atomicAdd(&cur1[d1[e]], 1); o1[p] = s1[e]; }
    { int p = atomicAdd(&cur2[d2[e]], 1); o2[p] = s2[e]; }
}

// ================= fold helpers =================
__device__ __forceinline__ float fold_elem(const float* __restrict__ W,
                                           const float* __restrict__ a,
                                           int H, int C, int t) {
    int k = t / H, h = t - k * H;
    const float* wr = W + (size_t)k * H * C + h * C;
    const float* ar = a + h * C;
    float s = 0.f;
    for (int c = 0; c < C; c++) s += wr[c] * ar[c];
    return s;
}
__device__ __forceinline__ float fold_dec_elem(const float* __restrict__ Ws,
                                               const float* __restrict__ dw1,
                                               int dec_off, int t) {
    int k = t >> 6, hj = t & 63;
    int h = hj >> 4, j = hj & 15;
    const float* wrow = Ws + (size_t)k * 512 + h * 128;
    const float* drow = dw1 + (size_t)(dec_off + h * 128) * 16 + j;
    float s = 0.f;
    for (int c = 0; c < 128; c++) s += wrow[c] * drow[c * 16];
    return s;
}

// front1: histogram | all weight folds (independent of each other)
__global__ void __launch_bounds__(256) front1_k(
    const int* um_dst, const int* mu_dst, int* cnt_um, int* cnt_mu,
    const float* w1um_s, const float* a1um_s, const float* w1mu_d, const float* a1mu_d,
    const float* w1um_d, const float* a1um_d, const float* w1mu_s, const float* a1mu_s,
    const float* w2um_s, const float* a2um_s, const float* w2mu_d, const float* a2mu_d,
    const float* w2um_d, const float* a2um_d, const float* w2mu_s, const float* a2mu_s,
    const float* dw1, const float* db1, const float* b2um, const float* b2mu,
    float* wa1, float* wa2, float* wa3, float* wa4,
    float* wb1, float* wb2, float* wb3, float* wb4,
    float* wfum, float* wfmu, float* bc) {
    int gb = blockIdx.x;
    if (gb < NB_HIST) {
        int e = gb * 256 + threadIdx.x;
        if (e < E) {
            atomicAdd(&cnt_um[um_dst[e]], 1);
            atomicAdd(&cnt_mu[mu_dst[e]], 1);
        }
    } else {
        int t = (gb - NB_HIST) * 256 + threadIdx.x;
        if (t >= PTOT) return;
        if (t < PO2)       wa1[t - PO1] = fold_elem(w1um_s, a1um_s, H1, C1, t - PO1);
        else if (t < PO3)  wa2[t - PO2] = fold_elem(w1mu_d, a1mu_d, H1, C1, t - PO2);
        else if (t < PO4)  wa3[t - PO3] = fold_elem(w1um_d, a1um_d, H1, C1, t - PO3);
        else if (t < PO5)  wa4[t - PO4] = fold_elem(w1mu_s, a1mu_s, H1, C1, t - PO4);
        else if (t < PO6)  wb1[t - PO5] = fold_elem(w2um_s, a2um_s, H2, C2, t - PO5);
        else if (t < PO7)  wb2[t - PO6] = fold_elem(w2mu_d, a2mu_d, H2, C2, t - PO6);
        else if (t < PO8)  wb3[t - PO7] = fold_elem(w2um_d, a2um_d, H2, C2, t - PO7);
        else if (t < PO9)  wb4[t - PO8] = fold_elem(w2mu_s, a2mu_s, H2, C2, t - PO8);
        else if (t < PO10) wfum[t - PO9]  = fold_dec_elem(w2um_s, dw1, 512, t - PO9);
        else if (t < PO11) wfmu[t - PO10] = fold_dec_elem(w2mu_s, dw1, 0,   t - PO10);
        else {
            int j = t - PO11;
            float s = db1[j];
            for (int d = 0; d < 512; d++)
                s += b2mu[d] * dw1[d * 16 + j] + b2um[d] * dw1[(512 + d) * 16 + j];
            bc[j] = s;
        }
    }
}

// ================= layer-1 scores (merged xu|xm), depends on front1 folds ======
template <int K>
__device__ void dev_scores2(const float* __restrict__ x,
                            const float* __restrict__ wa1, const float* __restrict__ wa2,
                            float* __restrict__ y1, float* __restrict__ y2, int n,
                            int bid, float* sh) {
    constexpr int H = 8;
    float* s1 = sh;
    float* s2 = sh + K * H;
    int t = threadIdx.x;
    for (int i = t; i < K * H; i += 256) { s1[i] = wa1[i]; s2[i] = wa2[i]; }
    __syncthreads();
    int warp = t >> 5, lane = t & 31;
    int node = bid * 8 + warp;
    if (node >= n) return;
    const float* row = x + (size_t)node * K;
    float a1[H] = {}, a2[H] = {};
#pragma unroll
    for (int k0 = 0; k0 < K; k0 += 32) {
        float xv = row[k0 + lane];
#pragma unroll
        for (int h = 0; h < H; h++) {
            a1[h] += xv * s1[(k0 + lane) * H + h];
            a2[h] += xv * s2[(k0 + lane) * H + h];
        }
    }
#pragma unroll
    for (int h = 0; h < H; h++) {
#pragma unroll
        for (int o = 16; o; o >>= 1) {
            a1[h] += __shfl_xor_sync(0xffffffffu, a1[h], o);
            a2[h] += __shfl_xor_sync(0xffffffffu, a2[h], o);
        }
    }
    if (lane == 0) {
#pragma unroll
        for (int h = 0; h < H; h++) {
            y1[(size_t)node * H + h] = a1[h];
            y2[(size_t)node * H + h] = a2[h];
        }
    }
}

__global__ void __launch_bounds__(256) front2_k(
    const float* xu, const float* xm,
    const float* wa1, const float* wa2, const float* wa3, const float* wa4,
    float* su1, float* su2, float* sm1, float* sm2) {
    __shared__ float sh[2048];
    int gb = blockIdx.x;
    if (gb < NB_SXU)
        dev_scores2<FU>(xu, wa1, wa2, su1, su2, NU, gb, sh);
    else
        dev_scores2<FM>(xm, wa3, wa4, sm1, sm2, NM, gb - NB_SXU, sh);
}

// ================= sgemm for hs1mu (standalone) =================
__global__ void sgemm_k(const float* __restrict__ A, int lda,
                        const float* __restrict__ B, int ldb,
                        float* __restrict__ C, int ldc, int M, int K) {
    __shared__ float As[8][128];
    __shared__ float Bs[8][128];
    int t  = threadIdx.x;
    int tx = t & 15, ty = t >> 4;
    int row0 = blockIdx.y * 128, col0 = blockIdx.x * 128;
    float acc[8][8] = {};
    for (int k0 = 0; k0 < K; k0 += 8) {
        {
            int m = t >> 1, k4 = (t & 1) * 4;
            int r = row0 + m;
            float4 v = make_float4(0.f, 0.f, 0.f, 0.f);
            if (r < M) v = *(const float4*)&A[(size_t)r * lda + k0 + k4];
            As[k4 + 0][m] = v.x; As[k4 + 1][m] = v.y;
            As[k4 + 2][m] = v.z; As[k4 + 3][m] = v.w;
        }
        {
            int kk = t >> 5, n4 = (t & 31) * 4;
            *(float4*)&Bs[kk][n4] = *(const float4*)&B[(size_t)(k0 + kk) * ldb + col0 + n4];
        }
        __syncthreads();
#pragma unroll
        for (int kk = 0; kk < 8; kk++) {
            float a_[8], b_[8];
            *(float4*)&a_[0] = *(const float4*)&As[kk][ty * 8];
            *(float4*)&a_[4] = *(const float4*)&As[kk][ty * 8 + 4];
            *(float4*)&b_[0] = *(const float4*)&Bs[kk][tx * 8];
            *(float4*)&b_[4] = *(const float4*)&Bs[kk][tx * 8 + 4];
#pragma unroll
            for (int i = 0; i < 8; i++)
#pragma unroll
                for (int j = 0; j < 8; j++) acc[i][j] += a_[i] * b_[j];
        }
        __syncthreads();
    }
    for (int i = 0; i < 8; i++) {
        int r = row0 + ty * 8 + i;
        if (r >= M) break;
#pragma unroll
        for (int j4 = 0; j4 < 8; j4 += 4) {
            float4 v = make_float4(acc[i][j4], acc[i][j4 + 1], acc[i][j4 + 2], acc[i][j4 + 3]);
            *(float4*)&C[(size_t)r * ldc + col0 + tx * 8 + j4] = v;
        }
    }
}

// ================= layer-1 aggregations =================
__device__ void dev_aggr_pre_l1(const int* __restrict__ rowptr, const int* __restrict__ csr,
                                const float* __restrict__ es, const float* __restrict__ ed,
                                const float* __restrict__ xu, float* __restrict__ agg,
                                int nd, int bid) {
    int w = bid * 8 + (threadIdx.x >> 5);
    int lane = threadIdx.x & 31;
    if (w >= nd) return;
    int rs = rowptr[w], re = rowptr[w + 1];
    float edv[8], m[8], ssum[8], acc[8];
    {
        float4 e0 = *(const float4*)&ed[(size_t)w * 8];
        float4 e1 = *(const float4*)&ed[(size_t)w * 8 + 4];
        edv[0]=e0.x; edv[1]=e0.y; edv[2]=e0.z; edv[3]=e0.w;
        edv[4]=e1.x; edv[5]=e1.y; edv[6]=e1.z; edv[7]=e1.w;
    }
#pragma unroll
    for (int h = 0; h < 8; h++) { m[h] = -INFINITY; ssum[h] = 0.f; acc[h] = 0.f; }
    for (int i = rs + lane; i < re; i += 32) {
        int s = csr[i];
        float4 v0 = *(const float4*)&es[(size_t)s * 8];
        float4 v1 = *(const float4*)&es[(size_t)s * 8 + 4];
        float ev[8] = { v0.x, v0.y, v0.z, v0.w, v1.x, v1.y, v1.z, v1.w };
#pragma unroll
        for (int h = 0; h < 8; h++) {
            float e = ev[h] + edv[h];
            e = e > 0.f ? e : 0.2f * e;
            m[h] = fmaxf(m[h], e);
        }
    }
#pragma unroll
    for (int h = 0; h < 8; h++)
#pragma unroll
        for (int o = 16; o; o >>= 1) m[h] = fmaxf(m[h], __shfl_xor_sync(0xffffffffu, m[h], o));
    for (int i = rs; i < re; i++) {
        int s = csr[i];
        float xv = xu[(size_t)s * 32 + lane];
        float4 v0 = *(const float4*)&es[(size_t)s * 8];
        float4 v1 = *(const float4*)&es[(size_t)s * 8 + 4];
        float ev[8] = { v0.x, v0.y, v0.z, v0.w, v1.x, v1.y, v1.z, v1.w };
#pragma unroll
        for (int h = 0; h < 8; h++) {
            float e = ev[h] + edv[h];
            e = e > 0.f ? e : 0.2f * e;
            float a = __expf(e - m[h]);
            ssum[h] += a;
            acc[h] += a * xv;
        }
    }
#pragma unroll
    for (int h = 0; h < 8; h++)
        agg[(size_t)w * 256 + h * 32 + lane] = acc[h] * (1.f / (ssum[h] + 1e-16f));
}

__device__ void dev_aggr_l1mu(const int* __restrict__ rowptr, const int* __restrict__ csr,
                              const float* __restrict__ es, const float* __restrict__ ed,
                              const float* __restrict__ feat, const float* __restrict__ bias,
                              float* __restrict__ out, int nd, int bid) {
    int w = bid * 8 + (threadIdx.x >> 5);
    int lane = threadIdx.x & 31;
    if (w >= nd) return;
    int rs = rowptr[w], re = rowptr[w + 1];
    float edv[8], m[8];
    {
        float4 e0 = *(const float4*)&ed[(size_t)w * 8];
        float4 e1 = *(const float4*)&ed[(size_t)w * 8 + 4];
        edv[0]=e0.x; edv[1]=e0.y; edv[2]=e0.z; edv[3]=e0.w;
        edv[4]=e1.x; edv[5]=e1.y; edv[6]=e1.z; edv[7]=e1.w;
    }
#pragma unroll
    for (int h = 0; h < 8; h++) m[h] = -INFINITY;
    for (int i = rs + lane; i < re; i += 32) {
        int s = csr[i];
        float4 v0 = *(const float4*)&es[(size_t)s * 8];
        float4 v1 = *(const float4*)&es[(size_t)s * 8 + 4];
        float ev[8] = { v0.x, v0.y, v0.z, v0.w, v1.x, v1.y, v1.z, v1.w };
#pragma unroll
        for (int h = 0; h < 8; h++) {
            float e = ev[h] + edv[h];
            e = e > 0.f ? e : 0.2f * e;
            m[h] = fmaxf(m[h], e);
        }
    }
#pragma unroll
    for (int h = 0; h < 8; h++)
#pragma unroll
        for (int o = 16; o; o >>= 1) m[h] = fmaxf(m[h], __shfl_xor_sync(0xffffffffu, m[h], o));
    int hh = lane >> 2;
    float edh = edv[hh], mh = m[hh];
    float ssum = 0.f;
    float4 acc = make_float4(0.f, 0.f, 0.f, 0.f);
    for (int i = rs; i < re; i++) {
        int s = csr[i];
        float e = es[(size_t)s * 8 + hh] + edh;
        e = e > 0.f ? e : 0.2f * e;
        float a = __expf(e - mh);
        ssum += a;
        float4 x = *(const float4*)&feat[(size_t)s * 128 + lane * 4];
        acc.x += a * x.x; acc.y += a * x.y;
        acc.z += a * x.z; acc.w += a * x.w;
    }
    float sinv = 1.f / (ssum + 1e-16f);
    float4 bb = *(const float4*)&bias[lane * 4];
    float4 o = make_float4(fmaxf(acc.x * sinv + bb.x, 0.f), fmaxf(acc.y * sinv + bb.y, 0.f),
                           fmaxf(acc.z * sinv + bb.z, 0.f), fmaxf(acc.w * sinv + bb.w, 0.f));
    *(float4*)&out[(size_t)w * 128 + lane * 4] = o;
}

__global__ void __launch_bounds__(256) fused_aggr1_k(
    const int* rp_um, const int* csr_um, const float* su1, const float* sm1,
    const float* xu, float* agg1,
    const int* rp_mu, const int* csr_mu, const float* sm2, const float* su2,
    const float* hs1mu, const float* b1mu, float* zu) {
    int gb = blockIdx.x;
    if (gb < NB_AG_UM)
        dev_aggr_pre_l1(rp_um, csr_um, su1, sm1, xu, agg1, NM, gb);
    else
        dev_aggr_l1mu(rp_mu, csr_mu, sm2, su2, hs1mu, b1mu, zu, NU, gb - NB_AG_UM);
}

// ================= mid: l1post | proj64+scores =================
__device__ void dev_l1post(const float* __restrict__ agg, const float* __restrict__ W,
                           const float* __restrict__ b, float* __restrict__ zm, int n,
                           int bid, float* sh) {
    float* ws = sh;          // 32*128
    float* bs = sh + 4096;   // 128
    for (int i = threadIdx.x; i < 32 * 128 / 4; i += 256)
        ((float4*)ws)[i] = ((const float4*)W)[i];
    if (threadIdx.x < 32) ((float4*)bs)[threadIdx.x] = ((const float4*)b)[threadIdx.x];
    __syncthreads();
    int j = threadIdx.x & 127;
    int half = threadIdx.x >> 7;
    int h = j >> 4;
    for (int r = bid * 2 + half; r < n; r += NB_L1POST * 2) {
        const float* arow = agg + (size_t)r * 256 + h * 32;
        float s = bs[j];
#pragma unroll
        for (int k = 0; k < 32; k++) s += arow[k] * ws[k * 128 + j];
        zm[(size_t)r * 128 + j] = fmaxf(s, 0.f);
    }
}

__device__ void dev_proj64s(const float* __restrict__ X, const float* __restrict__ Wf,
                            const float* __restrict__ wbA, const float* __restrict__ wbB,
                            float* __restrict__ Y, float* __restrict__ y1, float* __restrict__ y2,
                            int M, int bid, float* sh) {
    float* As = sh;            // 16*132 = 2112
    float* Bs = sh + 2112;     // 16*64  = 1024
    float* Wb = sh + 3136;     // 128*8  = 1024
    int t = threadIdx.x;
    for (int i = t; i < 128 * 4; i += 256) {
        Wb[(i >> 2) * 8 + (i & 3)]     = wbA[i];
        Wb[(i >> 2) * 8 + 4 + (i & 3)] = wbB[i];
    }
    int tx = t & 15, ty = t >> 4;
    int row0 = bid * 128;
    float acc[8][4] = {};
    float accs[8] = {};
    for (int k0 = 0; k0 < 128; k0 += 16) {
#pragma unroll
        for (int l = 0; l < 2; l++) {
            int i = t * 2 + l;
            int row = i >> 2, k4 = (i & 3) * 4;
            int r = row0 + row;
            float4 v = make_float4(0.f, 0.f, 0.f, 0.f);
            if (r < M) v = *(const float4*)&X[(size_t)r * 128 + k0 + k4];
            As[(k4 + 0) * 132 + row] = v.x; As[(k4 + 1) * 132 + row] = v.y;
            As[(k4 + 2) * 132 + row] = v.z; As[(k4 + 3) * 132 + row] = v.w;
        }
        {
            int kk = t >> 4, c4 = (t & 15) * 4;
            *(float4*)&Bs[kk * 64 + c4] = *(const float4*)&Wf[(size_t)(k0 + kk) * 64 + c4];
        }
        __syncthreads();
#pragma unroll
        for (int kk = 0; kk < 16; kk++) {
            float a_[8], b_[4];
            *(float4*)&a_[0] = *(const float4*)&As[kk * 132 + ty * 8];
            *(float4*)&a_[4] = *(const float4*)&As[kk * 132 + ty * 8 + 4];
            *(float4*)&b_[0] = *(const float4*)&Bs[kk * 64 + tx * 4];
#pragma unroll
            for (int i = 0; i < 8; i++)
#pragma unroll
                for (int j = 0; j < 4; j++) acc[i][j] += a_[i] * b_[j];
            if (tx < 8) {
                float bsv = Wb[(k0 + kk) * 8 + tx];
#pragma unroll
                for (int i = 0; i < 8; i++) accs[i] += a_[i] * bsv;
            }
        }
        __syncthreads();
    }
    for (int i = 0; i < 8; i++) {
        int r = row0 + ty * 8 + i;
        if (r >= M) break;
        *(float4*)&Y[(size_t)r * 64 + tx * 4] =
            make_float4(acc[i][0], acc[i][1], acc[i][2], acc[i][3]);
        if (tx < 4)       y1[(size_t)r * 4 + tx] = accs[i];
        else if (tx < 8)  y2[(size_t)r * 4 + tx - 4] = accs[i];
    }
}

__global__ void __launch_bounds__(256) fused_mid_k(
    const float* agg1, const float* w1um_s, const float* b1um, float* zm,
    const float* zu, const float* wfum, const float* wb1, const float* wb2,
    float* psu, float* su1, float* su2) {
    __shared__ float sh[4224];
    int gb = blockIdx.x;
    if (gb < NB_L1POST)
        dev_l1post(agg1, w1um_s, b1um, zm, NM, gb, sh);
    else
        dev_proj64s(zu, wfum, wb1, wb2, psu, su1, su2, NU, gb - NB_L1POST, sh);
}

__global__ void __launch_bounds__(256) proj64s_k(
    const float* X, const float* Wf, const float* wbA, const float* wbB,
    float* Y, float* y1, float* y2, int M) {
    __shared__ float sh[4224];
    dev_proj64s(X, Wf, wbA, wbB, Y, y1, y2, M, blockIdx.x, sh);
}

// ================= layer-2 aggregation (merged um+mu) =================
__device__ void dev_aggr16(const int* __restrict__ rowptr, const int* __restrict__ csr,
                           const float* __restrict__ es, const float* __restrict__ ed,
                           const float* __restrict__ ps, float* __restrict__ out,
                           int nd, int bid) {
    int w = bid * 8 + (threadIdx.x >> 5);
    int lane = threadIdx.x & 31;
    if (w >= nd) return;
    int rs = rowptr[w], re = rowptr[w + 1];
    float edv[4], m[4];
    {
        float4 e0 = *(const float4*)&ed[(size_t)w * 4];
        edv[0]=e0.x; edv[1]=e0.y; edv[2]=e0.z; edv[3]=e0.w;
    }
#pragma unroll
    for (int h = 0; h < 4; h++) m[h] = -INFINITY;
    for (int i = rs + lane; i < re; i += 32) {
        int s = csr[i];
        float4 ev = *(const float4*)&es[(size_t)s * 4];
        float e4[4] = { ev.x, ev.y, ev.z, ev.w };
#pragma unroll
        for (int h = 0; h < 4; h++) {
            float e = e4[h] + edv[h];
            e = e > 0.f ? e : 0.2f * e;
            m[h] = fmaxf(m[h], e);
        }
    }
#pragma unroll
    for (int h = 0; h < 4; h++)
#pragma unroll
        for (int o = 16; o; o >>= 1) m[h] = fmaxf(m[h], __shfl_xor_sync(0xffffffffu, m[h], o));
    int hh = lane >> 3;
    float edh = edv[hh], mh = m[hh];
    float ssum = 0.f, ax = 0.f, ay = 0.f;
    for (int i = rs; i < re; i++) {
        int s = csr[i];
        float e = es[(size_t)s * 4 + hh] + edh;
        e = e > 0.f ? e : 0.2f * e;
        float a = __expf(e - mh);
        ssum += a;
        float2 v = *(const float2*)&ps[(size_t)s * 64 + lane * 2];
        ax += a * v.x; ay += a * v.y;
    }
    float sinv = 1.f / (ssum + 1e-16f);
    ax *= sinv; ay *= sinv;
    ax += __shfl_xor_sync(0xffffffffu, ax, 8);
    ay += __shfl_xor_sync(0xffffffffu, ay, 8);
    ax += __shfl_xor_sync(0xffffffffu, ax, 16);
    ay += __shfl_xor_sync(0xffffffffu, ay, 16);
    if (lane < 8) *(float2*)&out[(size_t)w * 16 + lane * 2] = make_float2(ax, ay);
}

__global__ void __launch_bounds__(256) fused_aggr2_k(
    const int* rp_um, const int* csr_um, const float* su1, const float* sm1,
    const float* psu, float* pm,
    const int* rp_mu, const int* csr_mu, const float* sm2, const float* su2,
    const float* psm, float* pu) {
    int gb = blockIdx.x;
    if (gb < NB_AG_UM)
        dev_aggr16(rp_um, csr_um, su1, sm1, psu, pm, NM, gb);
    else
        dev_aggr16(rp_mu, csr_mu, sm2, su2, psm, pu, NU, gb - NB_AG_UM);
}

// ================= decoder =================
__global__ void dec_edge_k(const float* __restrict__ pu, const float* __restrict__ pm,
                           const int* __restrict__ lu, const int* __restrict__ lm,
                           const float* __restrict__ bc, const float* __restrict__ dw2,
                           const float* __restrict__ db2, float* __restrict__ out, int M) {
    int e = blockIdx.x * blockDim.x + threadIdx.x;
    if (e >= M) return;
    const float4* a = (const float4*)&pu[(size_t)lu[e] * 16];
    const float4* b = (const float4*)&pm[(size_t)lm[e] * 16];
    float acc = db2[0];
#pragma unroll
    for (int q = 0; q < 4; q++) {
        float4 av = a[q], bv = b[q];
        float4 dv = ((const float4*)bc)[q], wv = ((const float4*)dw2)[q];
        acc += fmaxf(av.x + bv.x + dv.x, 0.f) * wv.x;
        acc += fmaxf(av.y + bv.y + dv.y, 0.f) * wv.y;
        acc += fmaxf(av.z + bv.z + dv.z, 0.f) * wv.z;
        acc += fmaxf(av.w + bv.w + dv.w, 0.f) * wv.w;
    }
    out[e] = acc;
}

// ---------------- launch --------------------------------------------------------
extern "C" void kernel_launch(void* const* d_in, const int* in_sizes, int n_in,
                              void* d_out, int out_size) {
    const float* xu     = (const float*)d_in[0];
    const float* xm     = (const float*)d_in[1];
    const int*   um_src = (const int*)d_in[2];
    const int*   um_dst = (const int*)d_in[3];
    const int*   mu_src = (const int*)d_in[4];
    const int*   mu_dst = (const int*)d_in[5];
    const int*   lab_u  = (const int*)d_in[6];
    const int*   lab_m  = (const int*)d_in[7];
    const float* w1um_s = (const float*)d_in[8];
    const float* w1um_d = (const float*)d_in[9];
    const float* a1um_s = (const float*)d_in[10];
    const float* a1um_d = (const float*)d_in[11];
    const float* b1um   = (const float*)d_in[12];
    const float* w1mu_s = (const float*)d_in[13];
    const float* w1mu_d = (const float*)d_in[14];
    const float* a1mu_s = (const float*)d_in[15];
    const float* a1mu_d = (const float*)d_in[16];
    const float* b1mu   = (const float*)d_in[17];
    const float* w2um_s = (const float*)d_in[18];
    const float* w2um_d = (const float*)d_in[19];
    const float* a2um_s = (const float*)d_in[20];
    const float* a2um_d = (const float*)d_in[21];
    const float* b2um   = (const float*)d_in[22];
    const float* w2mu_s = (const float*)d_in[23];
    const float* w2mu_d = (const float*)d_in[24];
    const float* a2mu_s = (const float*)d_in[25];
    const float* a2mu_d = (const float*)d_in[26];
    const float* b2mu   = (const float*)d_in[27];
    const float* dw1    = (const float*)d_in[28];
    const float* db1    = (const float*)d_in[29];
    const float* dw2    = (const float*)d_in[30];
    const float* db2    = (const float*)d_in[31];
    float* out = (float*)d_out;

    float *agg1, *hs1mu, *zu, *zm, *psu, *psm, *pu, *pm;
    float *su1, *su2, *sm1, *sm2;
    float *wa1, *wa2, *wa3, *wa4, *wb1, *wb2, *wb3, *wb4, *wfum, *wfmu, *bc;
    int *rp_um, *rp_mu, *csr_um, *csr_mu, *cnt, *bsum;
    cudaGetSymbolAddress((void**)&agg1,  g_agg1);
    cudaGetSymbolAddress((void**)&hs1mu, g_hs1mu);
    cudaGetSymbolAddress((void**)&zu,  g_zu);
    cudaGetSymbolAddress((void**)&zm,  g_zm);
    cudaGetSymbolAddress((void**)&psu, g_psu);
    cudaGetSymbolAddress((void**)&psm, g_psm);
    cudaGetSymbolAddress((void**)&pu,  g_pu);
    cudaGetSymbolAddress((void**)&pm,  g_pm);
    cudaGetSymbolAddress((void**)&su1, g_su1);
    cudaGetSymbolAddress((void**)&su2, g_su2);
    cudaGetSymbolAddress((void**)&sm1, g_sm1);
    cudaGetSymbolAddress((void**)&sm2, g_sm2);
    cudaGetSymbolAddress((void**)&wa1, g_wa1);
    cudaGetSymbolAddress((void**)&wa2, g_wa2);
    cudaGetSymbolAddress((void**)&wa3, g_wa3);
    cudaGetSymbolAddress((void**)&wa4, g_wa4);
    cudaGetSymbolAddress((void**)&wb1, g_wb1);
    cudaGetSymbolAddress((void**)&wb2, g_wb2);
    cudaGetSymbolAddress((void**)&wb3, g_wb3);
    cudaGetSymbolAddress((void**)&wb4, g_wb4);
    cudaGetSymbolAddress((void**)&wfum, g_wfum);
    cudaGetSymbolAddress((void**)&wfmu, g_wfmu);
    cudaGetSymbolAddress((void**)&bc,  g_bc);
    cudaGetSymbolAddress((void**)&rp_um, g_rp_um);
    cudaGetSymbolAddress((void**)&rp_mu, g_rp_mu);
    cudaGetSymbolAddress((void**)&csr_um, g_csr_um);
    cudaGetSymbolAddress((void**)&csr_mu, g_csr_mu);
    cudaGetSymbolAddress((void**)&cnt, g_cnt);
    cudaGetSymbolAddress((void**)&bsum, g_bsum);
    int* cnt_um = cnt;
    int* cnt_mu = cnt + NM;

    const int TB = 256;
    const int nb_um = ceil_div(NM, 1024), nb_mu = ceil_div(NU, 1024);

    // 1: zero degree counters (single combined memset)
    cudaMemsetAsync(cnt, 0, (NM + NU) * sizeof(int));
    // 2: sgemm hs1mu (independent of everything)
    sgemm_k<<<dim3(1, ceil_div(NM, 128)), 256>>>(xm, FM, w1mu_s, D1, hs1mu, D1, NM, FM);
    // 3: front1 = histogram | all weight folds
    front1_k<<<NB_F1, 256>>>(um_dst, mu_dst, cnt_um, cnt_mu,
                             w1um_s, a1um_s, w1mu_d, a1mu_d,
                             w1um_d, a1um_d, w1mu_s, a1mu_s,
                             w2um_s, a2um_s, w2mu_d, a2mu_d,
                             w2um_d, a2um_d, w2mu_s, a2mu_s,
                             dw1, db1, b2um, b2mu,
                             wa1, wa2, wa3, wa4, wb1, wb2, wb3, wb4,
                             wfum, wfmu, bc);
    // 4: front2 = layer-1 scores (xu | xm), depends on folds
    front2_k<<<NB_F2, 256>>>(xu, xm, wa1, wa2, wa3, wa4, su1, su2, sm1, sm2);
    // 5-8: CSR scan + scatter
    reduce2_k<<<nb_um + nb_mu, 256>>>(cnt_um, NM, nb_um, cnt_mu, NU, bsum);
    scan2_k<<<1, 64>>>(bsum, nb_um, nb_mu);
    blkscan2_k<<<nb_um + nb_mu, 256>>>(cnt_um, rp_um, NM, nb_um, E, cnt_mu, rp_mu, NU, E, bsum);
    scatter2_k<<<ceil_div(E, TB), TB>>>(um_src, um_dst, cnt_um, csr_um,
                                        mu_src, mu_dst, cnt_mu, csr_mu, E);
    // 9: layer-1 aggregations (um aggregate-first | mu fused)
    fused_aggr1_k<<<NB_AGGR, 256>>>(rp_um, csr_um, su1, sm1, xu, agg1,
                                    rp_mu, csr_mu, sm2, su2, hs1mu, b1mu, zu);
    // 10: l1post (zm) | proj64+scores (zu)
    fused_mid_k<<<NB_MID, 256>>>(agg1, w1um_s, b1um, zm,
                                 zu, wfum, wb1, wb2, psu, su1, su2);
    // 11: proj64+scores (zm)
    proj64s_k<<<NB_PROJM, 256>>>(zm, wfmu, wb3, wb4, psm, sm1, sm2, NM);
    // 12: layer-2 aggregations (um | mu)
    fused_aggr2_k<<<NB_AGGR, 256>>>(rp_um, csr_um, su1, sm1, psu, pm,
                                    rp_mu, csr_mu, sm2, su2, psm, pu);
    // 13: decoder
    dec_edge_k<<<ceil_div(EL, TB), TB>>>(pu, pm, lab_u, lab_m, bc, dw2, db2, out, EL);
}

// round 12
// speedup vs baseline: 4.6059x; 1.1502x over previous
#include <cuda_runtime.h>
#include <math.h>

// ---------------- problem constants ----------------
constexpr int NU = 100000, NM = 20000;
constexpr int FU = 32, FM = 128;
constexpr int H1 = 8, C1 = 16, D1 = 128;   // layer 1
constexpr int H2 = 4, C2 = 128, D2 = 512;  // layer 2
constexpr int E = 250000, EL = 200000;
constexpr int HID = 16;

// ---------------- device scratch ----------------
__device__ float g_hs1mu[(size_t)NM * D1];
__device__ float g_zu[(size_t)NU * D1];
__device__ float g_zm[(size_t)NM * D1];
__device__ float g_psu[(size_t)NU * 64];
__device__ float g_psm[(size_t)NM * 64];
__device__ float g_pu[(size_t)NU * HID];
__device__ float g_pm[(size_t)NM * HID];
__device__ float g_su1[(size_t)NU * H1];
__device__ float g_su2[(size_t)NU * H1];
__device__ float g_sm1[(size_t)NM * H1];
__device__ float g_sm2[(size_t)NM * H1];
__device__ float g_wa1[FU * H1];
__device__ float g_wa2[FU * H1];
__device__ float g_wa3[FM * H1];
__device__ float g_wa4[FM * H1];
__device__ float g_wb1[D1 * H2];
__device__ float g_wb2[D1 * H2];
__device__ float g_wb3[D1 * H2];
__device__ float g_wb4[D1 * H2];
__device__ float g_wfum[128 * 64];
__device__ float g_wfmu[128 * 64];
__device__ __align__(16) float g_bc[16];
// CSR
__device__ int g_rp_um[NM + 1];
__device__ int g_rp_mu[NU + 1];
__device__ int g_csr_um[E];
__device__ int g_csr_mu[E];
__device__ int g_cnt[NM + NU];
__device__ int g_bsum[256];

static inline int ceil_div(int a, int b) { return (a + b - 1) / b; }

// ---------------- prep sizing ----------------
constexpr int PO1 = 0,            PN1 = FU * H1;
constexpr int PO2 = PO1 + PN1,    PN2 = FU * H1;
constexpr int PO3 = PO2 + PN2,    PN3 = FM * H1;
constexpr int PO4 = PO3 + PN3,    PN4 = FM * H1;
constexpr int PO5 = PO4 + PN4,    PN5 = D1 * H2;
constexpr int PO6 = PO5 + PN5,    PN6 = D1 * H2;
constexpr int PO7 = PO6 + PN6,    PN7 = D1 * H2;
constexpr int PO8 = PO7 + PN7,    PN8 = D1 * H2;
constexpr int PO9 = PO8 + PN8,    PN9 = 128 * 64;
constexpr int PO10 = PO9 + PN9,   PN10 = 128 * 64;
constexpr int PO11 = PO10 + PN10, PN11 = 16;
constexpr int PTOT = PO11 + PN11;

// ---------------- dispatch block counts ----------------
constexpr int NB_SGEMM = (NM + 127) / 128;        // 157
constexpr int NB_HIST = (E + 255) / 256;          // 977
constexpr int NB_PREP = (PTOT + 255) / 256;       // 83
constexpr int NB_MEGA1 = NB_SGEMM + NB_HIST + NB_PREP;
constexpr int NB_SXU  = (NU + 7) / 8;             // 12500
constexpr int NB_SXM  = (NM + 7) / 8;             // 2500
constexpr int NB_RED  = 20 + 98;                  // nb_um + nb_mu (1024-elem blocks)
constexpr int NB_F2R = NB_SXU + NB_SXM + NB_RED;
constexpr int NB_AG_UM = (NM + 7) / 8;
constexpr int NB_AG_MU = (NU + 7) / 8;
constexpr int NB_AGGR = NB_AG_UM + NB_AG_MU;
constexpr int NB_PROJU = (NU + 127) / 128;
constexpr int NB_PROJM = (NM + 127) / 128;
constexpr int NB_PROJ2 = NB_PROJU + NB_PROJM;

// ================= CSR scan/scatter =================
__global__ void scan2_k(int* __restrict__ bsum, int nb1, int nb2) {
    int t = threadIdx.x;
    if (t == 0) {
        int acc = 0;
        for (int i = 0; i < nb1; i++) { int v = bsum[i]; bsum[i] = acc; acc += v; }
    } else if (t == 32) {
        int acc = 0;
        for (int i = 0; i < nb2; i++) { int v = bsum[128 + i]; bsum[128 + i] = acc; acc += v; }
    }
}

__global__ void blkscan2_k(int* __restrict__ deg1, int* __restrict__ rp1, int n1, int nb1, int ne1,
                           int* __restrict__ deg2, int* __restrict__ rp2, int n2, int ne2,
                           const int* __restrict__ bsum) {
    __shared__ int ts[256];
    int gb = blockIdx.x, tid = threadIdx.x;
    int* deg; int* rp; int n, b, bo, ne;
    if (gb < nb1) { deg = deg1; rp = rp1; n = n1; b = gb; bo = 0; ne = ne1; }
    else          { deg = deg2; rp = rp2; n = n2; b = gb - nb1; bo = 128; ne = ne2; }
    int base = b * 1024 + tid * 4;
    int v[4]; int loc = 0;
#pragma unroll
    for (int j = 0; j < 4; j++) { int idx = base + j; v[j] = (idx < n) ? deg[idx] : 0; loc += v[j]; }
    ts[tid] = loc; __syncthreads();
    for (int o = 1; o < 256; o <<= 1) {
        int t = (tid >= o) ? ts[tid - o] : 0;
        __syncthreads();
        ts[tid] += t;
        __syncthreads();
    }
    int excl = ts[tid] - loc + bsum[bo + b];
#pragma unroll
    for (int j = 0; j < 4; j++) {
        int idx = base + j;
        if (idx < n) { rp[idx] = excl; deg[idx] = excl; }
        excl += v[j];
    }
    if (b == 0 && tid == 0) rp[n] = ne;
}

__global__ void scatter2_k(const int* __restrict__ s1, const int* __restrict__ d1,
                           int* __restrict__ cur1, int* __restrict__ o1,
                           const int* __restrict__ s2, const int* __restrict__ d2,
                           int* __restrict__ cur2, int* __restrict__ o2, int ne) {
    int e = blockIdx.x * blockDim.x + threadIdx.x;
    if (e >= ne) return;
    { int p = atomicAdd(&cur1[d1[e]], 1); o1[p] = s1[e]; }
    { int p = atomicAdd(&cur2[d2[e]], 1); o2[p] = s2[e]; }
}

// ================= fold helpers =================
__device__ __forceinline__ float fold_elem(const float* __restrict__ W,
                                           const float* __restrict__ a,
                                           int H, int C, int t) {
    int k = t / H, h = t - k * H;
    const float* wr = W + (size_t)k * H * C + h * C;
    const float* ar = a + h * C;
    float s = 0.f;
    for (int c = 0; c < C; c++) s += wr[c] * ar[c];
    return s;
}
__device__ __forceinline__ float fold_dec_elem(const float* __restrict__ Ws,
                                               const float* __restrict__ dw1,
                                               int dec_off, int t) {
    int k = t >> 6, hj = t & 63;
    int h = hj >> 4, j = hj & 15;
    const float* wrow = Ws + (size_t)k * 512 + h * 128;
    const float* drow = dw1 + (size_t)(dec_off + h * 128) * 16 + j;
    float s = 0.f;
    for (int c = 0; c < 128; c++) s += wrow[c] * drow[c * 16];
    return s;
}

// ================= sgemm device fn (flattened bid, smem passed in) =============
__device__ void dev_sgemm(const float* __restrict__ A, int lda,
                          const float* __restrict__ B, int ldb,
                          float* __restrict__ C, int ldc, int M, int K,
                          int bid, float* sh) {
    float* As = sh;           // 8*128
    float* Bs = sh + 1024;    // 8*128
    int t  = threadIdx.x;
    int tx = t & 15, ty = t >> 4;
    int row0 = bid * 128;
    float acc[8][8] = {};
    for (int k0 = 0; k0 < K; k0 += 8) {
        {
            int m = t >> 1, k4 = (t & 1) * 4;
            int r = row0 + m;
            float4 v = make_float4(0.f, 0.f, 0.f, 0.f);
            if (r < M) v = *(const float4*)&A[(size_t)r * lda + k0 + k4];
            As[(k4 + 0) * 128 + m] = v.x; As[(k4 + 1) * 128 + m] = v.y;
            As[(k4 + 2) * 128 + m] = v.z; As[(k4 + 3) * 128 + m] = v.w;
        }
        {
            int kk = t >> 5, n4 = (t & 31) * 4;
            *(float4*)&Bs[kk * 128 + n4] = *(const float4*)&B[(size_t)(k0 + kk) * ldb + n4];
        }
        __syncthreads();
#pragma unroll
        for (int kk = 0; kk < 8; kk++) {
            float a_[8], b_[8];
            *(float4*)&a_[0] = *(const float4*)&As[kk * 128 + ty * 8];
            *(float4*)&a_[4] = *(const float4*)&As[kk * 128 + ty * 8 + 4];
            *(float4*)&b_[0] = *(const float4*)&Bs[kk * 128 + tx * 8];
            *(float4*)&b_[4] = *(const float4*)&Bs[kk * 128 + tx * 8 + 4];
#pragma unroll
            for (int i = 0; i < 8; i++)
#pragma unroll
                for (int j = 0; j < 8; j++) acc[i][j] += a_[i] * b_[j];
        }
        __syncthreads();
    }
    for (int i = 0; i < 8; i++) {
        int r = row0 + ty * 8 + i;
        if (r >= M) break;
#pragma unroll
        for (int j4 = 0; j4 < 8; j4 += 4) {
            float4 v = make_float4(acc[i][j4], acc[i][j4 + 1], acc[i][j4 + 2], acc[i][j4 + 3]);
            *(float4*)&C[(size_t)r * ldc + tx * 8 + j4] = v;
        }
    }
}

// ================= mega1: sgemm | hist | folds =================
__global__ void __launch_bounds__(256) mega1_k(
    const float* xm, const float* w1mu_s, float* hs1mu,
    const int* um_dst, const int* mu_dst, int* cnt_um, int* cnt_mu,
    const float* w1um_s, const float* a1um_s, const float* w1mu_d, const float* a1mu_d,
    const float* w1um_d, const float* a1um_d, const float* a1mu_s,
    const float* w2um_s, const float* a2um_s, const float* w2mu_d, const float* a2mu_d,
    const float* w2um_d, const float* a2um_d, const float* w2mu_s, const float* a2mu_s,
    const float* dw1, const float* db1, const float* b2um, const float* b2mu,
    float* wa1, float* wa2, float* wa3, float* wa4,
    float* wb1, float* wb2, float* wb3, float* wb4,
    float* wfum, float* wfmu, float* bc) {
    __shared__ float sh[2048];
    int gb = blockIdx.x;
    if (gb < NB_SGEMM) {
        dev_sgemm(xm, FM, w1mu_s, D1, hs1mu, D1, NM, FM, gb, sh);
    } else if (gb < NB_SGEMM + NB_HIST) {
        int e = (gb - NB_SGEMM) * 256 + threadIdx.x;
        if (e < E) {
            atomicAdd(&cnt_um[um_dst[e]], 1);
            atomicAdd(&cnt_mu[mu_dst[e]], 1);
        }
    } else {
        int t = (gb - NB_SGEMM - NB_HIST) * 256 + threadIdx.x;
        if (t >= PTOT) return;
        if (t < PO2)       wa1[t - PO1] = fold_elem(w1um_s, a1um_s, H1, C1, t - PO1);
        else if (t < PO3)  wa2[t - PO2] = fold_elem(w1mu_d, a1mu_d, H1, C1, t - PO2);
        else if (t < PO4)  wa3[t - PO3] = fold_elem(w1um_d, a1um_d, H1, C1, t - PO3);
        else if (t < PO5)  wa4[t - PO4] = fold_elem(w1mu_s, a1mu_s, H1, C1, t - PO4);
        else if (t < PO6)  wb1[t - PO5] = fold_elem(w2um_s, a2um_s, H2, C2, t - PO5);
        else if (t < PO7)  wb2[t - PO6] = fold_elem(w2mu_d, a2mu_d, H2, C2, t - PO6);
        else if (t < PO8)  wb3[t - PO7] = fold_elem(w2um_d, a2um_d, H2, C2, t - PO7);
        else if (t < PO9)  wb4[t - PO8] = fold_elem(w2mu_s, a2mu_s, H2, C2, t - PO8);
        else if (t < PO10) wfum[t - PO9]  = fold_dec_elem(w2um_s, dw1, 512, t - PO9);
        else if (t < PO11) wfmu[t - PO10] = fold_dec_elem(w2mu_s, dw1, 0,   t - PO10);
        else {
            int j = t - PO11;
            float s = db1[j];
            for (int d = 0; d < 512; d++)
                s += b2mu[d] * dw1[d * 16 + j] + b2um[d] * dw1[(512 + d) * 16 + j];
            bc[j] = s;
        }
    }
}

// ================= scores device fn =================
template <int K>
__device__ void dev_scores2(const float* __restrict__ x,
                            const float* __restrict__ wa1, const float* __restrict__ wa2,
                            float* __restrict__ y1, float* __restrict__ y2, int n,
                            int bid, float* sh) {
    constexpr int H = 8;
    float* s1 = sh;
    float* s2 = sh + K * H;
    int t = threadIdx.x;
    for (int i = t; i < K * H; i += 256) { s1[i] = wa1[i]; s2[i] = wa2[i]; }
    __syncthreads();
    int warp = t >> 5, lane = t & 31;
    int node = bid * 8 + warp;
    if (node >= n) return;
    const float* row = x + (size_t)node * K;
    float a1[H] = {}, a2[H] = {};
#pragma unroll
    for (int k0 = 0; k0 < K; k0 += 32) {
        float xv = row[k0 + lane];
#pragma unroll
        for (int h = 0; h < H; h++) {
            a1[h] += xv * s1[(k0 + lane) * H + h];
            a2[h] += xv * s2[(k0 + lane) * H + h];
        }
    }
#pragma unroll
    for (int h = 0; h < H; h++) {
#pragma unroll
        for (int o = 16; o; o >>= 1) {
            a1[h] += __shfl_xor_sync(0xffffffffu, a1[h], o);
            a2[h] += __shfl_xor_sync(0xffffffffu, a2[h], o);
        }
    }
    if (lane == 0) {
#pragma unroll
        for (int h = 0; h < H; h++) {
            y1[(size_t)node * H + h] = a1[h];
            y2[(size_t)node * H + h] = a2[h];
        }
    }
}

// ================= front2r: scores(xu) | scores(xm) | reduce2 =================
__global__ void __launch_bounds__(256) front2r_k(
    const float* xu, const float* xm,
    const float* wa1, const float* wa2, const float* wa3, const float* wa4,
    float* su1, float* su2, float* sm1, float* sm2,
    const int* cnt, int* bsum, int nb_um) {
    __shared__ float sh[2048];
    int gb = blockIdx.x;
    if (gb < NB_SXU) {
        dev_scores2<FU>(xu, wa1, wa2, su1, su2, NU, gb, sh);
    } else if (gb < NB_SXU + NB_SXM) {
        dev_scores2<FM>(xm, wa3, wa4, sm1, sm2, NM, gb - NB_SXU, sh);
    } else {
        int* shi = (int*)sh;
        int rb = gb - NB_SXU - NB_SXM;
        const int* deg; int n, b, bo;
        if (rb < nb_um) { deg = cnt; n = NM; b = rb; bo = 0; }
        else            { deg = cnt + NM; n = NU; b = rb - nb_um; bo = 128; }
        int tid = threadIdx.x;
        int base = b * 1024;
        int s = 0;
        for (int i = tid; i < 1024; i += 256) {
            int idx = base + i;
            if (idx < n) s += deg[idx];
        }
        shi[tid] = s; __syncthreads();
        for (int o = 128; o; o >>= 1) { if (tid < o) shi[tid] += shi[tid + o]; __syncthreads(); }
        if (tid == 0) bsum[bo + b] = shi[0];
    }
}

// ================= layer-1 aggregations (um fused with l1post) =================
// um: warp aggregates dst row into regs, then [32->16]-per-head matmul -> zm
__device__ void dev_aggr_um_fused(const int* __restrict__ rowptr, const int* __restrict__ csr,
                                  const float* __restrict__ es, const float* __restrict__ ed,
                                  const float* __restrict__ xu,
                                  float* __restrict__ zm, int nd, int bid, float* sh) {
    float* Wsh = sh;           // 32*128 = 4096 (loaded by caller)
    float* bsh = sh + 4096;    // 128
    float* vsh = sh + 4224;    // 8 warps * 264 (33-pad rows)
    int warp = threadIdx.x >> 5;
    int lane = threadIdx.x & 31;
    int w = bid * 8 + warp;
    if (w >= nd) return;
    int rs = rowptr[w], re = rowptr[w + 1];
    float edv[8], m[8], ssum[8], acc[8];
    {
        float4 e0 = *(const float4*)&ed[(size_t)w * 8];
        float4 e1 = *(const float4*)&ed[(size_t)w * 8 + 4];
        edv[0]=e0.x; edv[1]=e0.y; edv[2]=e0.z; edv[3]=e0.w;
        edv[4]=e1.x; edv[5]=e1.y; edv[6]=e1.z; edv[7]=e1.w;
    }
#pragma unroll
    for (int h = 0; h < 8; h++) { m[h] = -INFINITY; ssum[h] = 0.f; acc[h] = 0.f; }
    for (int i = rs + lane; i < re; i += 32) {
        int s = csr[i];
        float4 v0 = *(const float4*)&es[(size_t)s * 8];
        float4 v1 = *(const float4*)&es[(size_t)s * 8 + 4];
        float ev[8] = { v0.x, v0.y, v0.z, v0.w, v1.x, v1.y, v1.z, v1.w };
#pragma unroll
        for (int h = 0; h < 8; h++) {
            float e = ev[h] + edv[h];
            e = e > 0.f ? e : 0.2f * e;
            m[h] = fmaxf(m[h], e);
        }
    }
#pragma unroll
    for (int h = 0; h < 8; h++)
#pragma unroll
        for (int o = 16; o; o >>= 1) m[h] = fmaxf(m[h], __shfl_xor_sync(0xffffffffu, m[h], o));
    // merged expsum+feature pass, 2-way unrolled for MLP
    int i = rs;
    for (; i + 1 < re; i += 2) {
        int s0 = csr[i], s1 = csr[i + 1];
        float x0 = xu[(size_t)s0 * 32 + lane];
        float x1 = xu[(size_t)s1 * 32 + lane];
        float4 a0 = *(const float4*)&es[(size_t)s0 * 8];
        float4 a1 = *(const float4*)&es[(size_t)s0 * 8 + 4];
        float4 b0 = *(const float4*)&es[(size_t)s1 * 8];
        float4 b1 = *(const float4*)&es[(size_t)s1 * 8 + 4];
        float e0[8] = { a0.x, a0.y, a0.z, a0.w, a1.x, a1.y, a1.z, a1.w };
        float e1[8] = { b0.x, b0.y, b0.z, b0.w, b1.x, b1.y, b1.z, b1.w };
#pragma unroll
        for (int h = 0; h < 8; h++) {
            float u = e0[h] + edv[h]; u = u > 0.f ? u : 0.2f * u;
            float v = e1[h] + edv[h]; v = v > 0.f ? v : 0.2f * v;
            float au = __expf(u - m[h]);
            float av = __expf(v - m[h]);
            ssum[h] += au + av;
            acc[h] += au * x0 + av * x1;
        }
    }
    if (i < re) {
        int s = csr[i];
        float xv = xu[(size_t)s * 32 + lane];
        float4 v0 = *(const float4*)&es[(size_t)s * 8];
        float4 v1 = *(const float4*)&es[(size_t)s * 8 + 4];
        float ev[8] = { v0.x, v0.y, v0.z, v0.w, v1.x, v1.y, v1.z, v1.w };
#pragma unroll
        for (int h = 0; h < 8; h++) {
            float e = ev[h] + edv[h];
            e = e > 0.f ? e : 0.2f * e;
            float a = __expf(e - m[h]);
            ssum[h] += a;
            acc[h] += a * xv;
        }
    }
    float* vw = vsh + warp * 264;
#pragma unroll
    for (int h = 0; h < 8; h++)
        vw[h * 33 + lane] = acc[h] * (1.f / (ssum[h] + 1e-16f));
    __syncwarp();
    // epilogue: lane computes zm cols lane*4..+3; head = lane>>2
    const float* arow = vw + (lane >> 2) * 33;
    float4 o = *(const float4*)&bsh[lane * 4];
#pragma unroll
    for (int k = 0; k < 32; k++) {
        float av = arow[k];
        float4 wv = *(const float4*)&Wsh[k * 128 + lane * 4];
        o.x += av * wv.x; o.y += av * wv.y;
        o.z += av * wv.z; o.w += av * wv.w;
    }
    o.x = fmaxf(o.x, 0.f); o.y = fmaxf(o.y, 0.f);
    o.z = fmaxf(o.z, 0.f); o.w = fmaxf(o.w, 0.f);
    *(float4*)&zm[(size_t)w * 128 + lane * 4] = o;
}

__device__ void dev_aggr_l1mu(const int* __restrict__ rowptr, const int* __restrict__ csr,
                              const float* __restrict__ es, const float* __restrict__ ed,
                              const float* __restrict__ feat, const float* __restrict__ bias,
                              float* __restrict__ out, int nd, int bid) {
    int w = bid * 8 + (threadIdx.x >> 5);
    int lane = threadIdx.x & 31;
    if (w >= nd) return;
    int rs = rowptr[w], re = rowptr[w + 1];
    float edv[8], m[8];
    {
        float4 e0 = *(const float4*)&ed[(size_t)w * 8];
        float4 e1 = *(const float4*)&ed[(size_t)w * 8 + 4];
        edv[0]=e0.x; edv[1]=e0.y; edv[2]=e0.z; edv[3]=e0.w;
        edv[4]=e1.x; edv[5]=e1.y; edv[6]=e1.z; edv[7]=e1.w;
    }
#pragma unroll
    for (int h = 0; h < 8; h++) m[h] = -INFINITY;
    for (int i = rs + lane; i < re; i += 32) {
        int s = csr[i];
        float4 v0 = *(const float4*)&es[(size_t)s * 8];
        float4 v1 = *(const float4*)&es[(size_t)s * 8 + 4];
        float ev[8] = { v0.x, v0.y, v0.z, v0.w, v1.x, v1.y, v1.z, v1.w };
#pragma unroll
        for (int h = 0; h < 8; h++) {
            float e = ev[h] + edv[h];
            e = e > 0.f ? e : 0.2f * e;
            m[h] = fmaxf(m[h], e);
        }
    }
#pragma unroll
    for (int h = 0; h < 8; h++)
#pragma unroll
        for (int o = 16; o; o >>= 1) m[h] = fmaxf(m[h], __shfl_xor_sync(0xffffffffu, m[h], o));
    int hh = lane >> 2;
    float edh = edv[hh], mh = m[hh];
    float ssum = 0.f;
    float4 acc = make_float4(0.f, 0.f, 0.f, 0.f);
    int i = rs;
    for (; i + 1 < re; i += 2) {
        int s0 = csr[i], s1 = csr[i + 1];
        float e0 = es[(size_t)s0 * 8 + hh] + edh;
        float e1 = es[(size_t)s1 * 8 + hh] + edh;
        float4 x0 = *(const float4*)&feat[(size_t)s0 * 128 + lane * 4];
        float4 x1 = *(const float4*)&feat[(size_t)s1 * 128 + lane * 4];
        e0 = e0 > 0.f ? e0 : 0.2f * e0;
        e1 = e1 > 0.f ? e1 : 0.2f * e1;
        float a0 = __expf(e0 - mh);
        float a1 = __expf(e1 - mh);
        ssum += a0 + a1;
        acc.x += a0 * x0.x + a1 * x1.x; acc.y += a0 * x0.y + a1 * x1.y;
        acc.z += a0 * x0.z + a1 * x1.z; acc.w += a0 * x0.w + a1 * x1.w;
    }
    if (i < re) {
        int s = csr[i];
        float e = es[(size_t)s * 8 + hh] + edh;
        e = e > 0.f ? e : 0.2f * e;
        float a = __expf(e - mh);
        ssum += a;
        float4 x = *(const float4*)&feat[(size_t)s * 128 + lane * 4];
        acc.x += a * x.x; acc.y += a * x.y;
        acc.z += a * x.z; acc.w += a * x.w;
    }
    float sinv = 1.f / (ssum + 1e-16f);
    float4 bb = *(const float4*)&bias[lane * 4];
    float4 o = make_float4(fmaxf(acc.x * sinv + bb.x, 0.f), fmaxf(acc.y * sinv + bb.y, 0.f),
                           fmaxf(acc.z * sinv + bb.z, 0.f), fmaxf(acc.w * sinv + bb.w, 0.f));
    *(float4*)&out[(size_t)w * 128 + lane * 4] = o;
}

__global__ void __launch_bounds__(256) fused_aggr1_k(
    const int* rp_um, const int* csr_um, const float* su1, const float* sm1,
    const float* xu, const float* w1um_s, const float* b1um, float* zm,
    const int* rp_mu, const int* csr_mu, const float* sm2, const float* su2,
    const float* hs1mu, const float* b1mu, float* zu) {
    __shared__ float sh[6336];   // 4096 W + 128 bias + 8*264 v
    int gb = blockIdx.x;
    if (gb < NB_AG_UM) {
        // load W + bias once per block
        for (int i = threadIdx.x; i < 1024; i += 256)
            ((float4*)sh)[i] = ((const float4*)w1um_s)[i];
        if (threadIdx.x < 32) ((float4*)(sh + 4096))[threadIdx.x] = ((const float4*)b1um)[threadIdx.x];
        __syncthreads();
        dev_aggr_um_fused(rp_um, csr_um, su1, sm1, xu, zm, NM, gb, sh);
    } else {
        dev_aggr_l1mu(rp_mu, csr_mu, sm2, su2, hs1mu, b1mu, zu, NU, gb - NB_AG_UM);
    }
}

// ================= proj64 + scores (merged zu | zm) =================
__device__ void dev_proj64s(const float* __restrict__ X, const float* __restrict__ Wf,
                            const float* __restrict__ wbA, const float* __restrict__ wbB,
                            float* __restrict__ Y, float* __restrict__ y1, float* __restrict__ y2,
                            int M, int bid, float* sh) {
    float* As = sh;            // 16*132
    float* Bs = sh + 2112;     // 16*64
    float* Wb = sh + 3136;     // 128*8
    int t = threadIdx.x;
    for (int i = t; i < 128 * 4; i += 256) {
        Wb[(i >> 2) * 8 + (i & 3)]     = wbA[i];
        Wb[(i >> 2) * 8 + 4 + (i & 3)] = wbB[i];
    }
    int tx = t & 15, ty = t >> 4;
    int row0 = bid * 128;
    float acc[8][4] = {};
    float accs[8] = {};
    for (int k0 = 0; k0 < 128; k0 += 16) {
#pragma unroll
        for (int l = 0; l < 2; l++) {
            int i = t * 2 + l;
            int row = i >> 2, k4 = (i & 3) * 4;
            int r = row0 + row;
            float4 v = make_float4(0.f, 0.f, 0.f, 0.f);
            if (r < M) v = *(const float4*)&X[(size_t)r * 128 + k0 + k4];
            As[(k4 + 0) * 132 + row] = v.x; As[(k4 + 1) * 132 + row] = v.y;
            As[(k4 + 2) * 132 + row] = v.z; As[(k4 + 3) * 132 + row] = v.w;
        }
        {
            int kk = t >> 4, c4 = (t & 15) * 4;
            *(float4*)&Bs[kk * 64 + c4] = *(const float4*)&Wf[(size_t)(k0 + kk) * 64 + c4];
        }
        __syncthreads();
#pragma unroll
        for (int kk = 0; kk < 16; kk++) {
            float a_[8], b_[4];
            *(float4*)&a_[0] = *(const float4*)&As[kk * 132 + ty * 8];
            *(float4*)&a_[4] = *(const float4*)&As[kk * 132 + ty * 8 + 4];
            *(float4*)&b_[0] = *(const float4*)&Bs[kk * 64 + tx * 4];
#pragma unroll
            for (int i = 0; i < 8; i++)
#pragma unroll
                for (int j = 0; j < 4; j++) acc[i][j] += a_[i] * b_[j];
            if (tx < 8) {
                float bsv = Wb[(k0 + kk) * 8 + tx];
#pragma unroll
                for (int i = 0; i < 8; i++) accs[i] += a_[i] * bsv;
            }
        }
        __syncthreads();
    }
    for (int i = 0; i < 8; i++) {
        int r = row0 + ty * 8 + i;
        if (r >= M) break;
        *(float4*)&Y[(size_t)r * 64 + tx * 4] =
            make_float4(acc[i][0], acc[i][1], acc[i][2], acc[i][3]);
        if (tx < 4)       y1[(size_t)r * 4 + tx] = accs[i];
        else if (tx < 8)  y2[(size_t)r * 4 + tx - 4] = accs[i];
    }
}

__global__ void __launch_bounds__(256) proj2_k(
    const float* zu, const float* wfum, const float* wb1, const float* wb2,
    float* psu, float* su1, float* su2,
    const float* zm, const float* wfmu, const float* wb3, const float* wb4,
    float* psm, float* sm1, float* sm2) {
    __shared__ float sh[4224];
    int gb = blockIdx.x;
    if (gb < NB_PROJU)
        dev_proj64s(zu, wfum, wb1, wb2, psu, su1, su2, NU, gb, sh);
    else
        dev_proj64s(zm, wfmu, wb3, wb4, psm, sm1, sm2, NM, gb - NB_PROJU, sh);
}

// ================= layer-2 aggregation (merged um+mu) =================
__device__ void dev_aggr16(const int* __restrict__ rowptr, const int* __restrict__ csr,
                           const float* __restrict__ es, const float* __restrict__ ed,
                           const float* __restrict__ ps, float* __restrict__ out,
                           int nd, int bid) {
    int w = bid * 8 + (threadIdx.x >> 5);
    int lane = threadIdx.x & 31;
    if (w >= nd) return;
    int rs = rowptr[w], re = rowptr[w + 1];
    float edv[4], m[4];
    {
        float4 e0 = *(const float4*)&ed[(size_t)w * 4];
        edv[0]=e0.x; edv[1]=e0.y; edv[2]=e0.z; edv[3]=e0.w;
    }
#pragma unroll
    for (int h = 0; h < 4; h++) m[h] = -INFINITY;
    for (int i = rs + lane; i < re; i += 32) {
        int s = csr[i];
        float4 ev = *(const float4*)&es[(size_t)s * 4];
        float e4[4] = { ev.x, ev.y, ev.z, ev.w };
#pragma unroll
        for (int h = 0; h < 4; h++) {
            float e = e4[h] + edv[h];
            e = e > 0.f ? e : 0.2f * e;
            m[h] = fmaxf(m[h], e);
        }
    }
#pragma unroll
    for (int h = 0; h < 4; h++)
#pragma unroll
        for (int o = 16; o; o >>= 1) m[h] = fmaxf(m[h], __shfl_xor_sync(0xffffffffu, m[h], o));
    int hh = lane >> 3;
    float edh = edv[hh], mh = m[hh];
    float ssum = 0.f, ax = 0.f, ay = 0.f;
    int i = rs;
    for (; i + 1 < re; i += 2) {
        int s0 = csr[i], s1 = csr[i + 1];
        float e0 = es[(size_t)s0 * 4 + hh] + edh;
        float e1 = es[(size_t)s1 * 4 + hh] + edh;
        float2 v0 = *(const float2*)&ps[(size_t)s0 * 64 + lane * 2];
        float2 v1 = *(const float2*)&ps[(size_t)s1 * 64 + lane * 2];
        e0 = e0 > 0.f ? e0 : 0.2f * e0;
        e1 = e1 > 0.f ? e1 : 0.2f * e1;
        float a0 = __expf(e0 - mh);
        float a1 = __expf(e1 - mh);
        ssum += a0 + a1;
        ax += a0 * v0.x + a1 * v1.x;
        ay += a0 * v0.y + a1 * v1.y;
    }
    if (i < re) {
        int s = csr[i];
        float e = es[(size_t)s * 4 + hh] + edh;
        e = e > 0.f ? e : 0.2f * e;
        float a = __expf(e - mh);
        ssum += a;
        float2 v = *(const float2*)&ps[(size_t)s * 64 + lane * 2];
        ax += a * v.x; ay += a * v.y;
    }
    float sinv = 1.f / (ssum + 1e-16f);
    ax *= sinv; ay *= sinv;
    ax += __shfl_xor_sync(0xffffffffu, ax, 8);
    ay += __shfl_xor_sync(0xffffffffu, ay, 8);
    ax += __shfl_xor_sync(0xffffffffu, ax, 16);
    ay += __shfl_xor_sync(0xffffffffu, ay, 16);
    if (lane < 8) *(float2*)&out[(size_t)w * 16 + lane * 2] = make_float2(ax, ay);
}

__global__ void __launch_bounds__(256) fused_aggr2_k(
    const int* rp_um, const int* csr_um, const float* su1, const float* sm1,
    const float* psu, float* pm,
    const int* rp_mu, const int* csr_mu, const float* sm2, const float* su2,
    const float* psm, float* pu) {
    int gb = blockIdx.x;
    if (gb < NB_AG_UM)
        dev_aggr16(rp_um, csr_um, su1, sm1, psu, pm, NM, gb);
    else
        dev_aggr16(rp_mu, csr_mu, sm2, su2, psm, pu, NU, gb - NB_AG_UM);
}

// ================= decoder =================
__global__ void dec_edge_k(const float* __restrict__ pu, const float* __restrict__ pm,
                           const int* __restrict__ lu, const int* __restrict__ lm,
                           const float* __restrict__ bc, const float* __restrict__ dw2,
                           const float* __restrict__ db2, float* __restrict__ out, int M) {
    int e = blockIdx.x * blockDim.x + threadIdx.x;
    if (e >= M) return;
    const float4* a = (const float4*)&pu[(size_t)lu[e] * 16];
    const float4* b = (const float4*)&pm[(size_t)lm[e] * 16];
    float acc = db2[0];
#pragma unroll
    for (int q = 0; q < 4; q++) {
        float4 av = a[q], bv = b[q];
        float4 dv = ((const float4*)bc)[q], wv = ((const float4*)dw2)[q];
        acc += fmaxf(av.x + bv.x + dv.x, 0.f) * wv.x;
        acc += fmaxf(av.y + bv.y + dv.y, 0.f) * wv.y;
        acc += fmaxf(av.z + bv.z + dv.z, 0.f) * wv.z;
        acc += fmaxf(av.w + bv.w + dv.w, 0.f) * wv.w;
    }
    out[e] = acc;
}

// ---------------- launch --------------------------------------------------------
extern "C" void kernel_launch(void* const* d_in, const int* in_sizes, int n_in,
                              void* d_out, int out_size) {
    const float* xu     = (const float*)d_in[0];
    const float* xm     = (const float*)d_in[1];
    const int*   um_src = (const int*)d_in[2];
    const int*   um_dst = (const int*)d_in[3];
    const int*   mu_src = (const int*)d_in[4];
    const int*   mu_dst = (const int*)d_in[5];
    const int*   lab_u  = (const int*)d_in[6];
    const int*   lab_m  = (const int*)d_in[7];
    const float* w1um_s = (const float*)d_in[8];
    const float* w1um_d = (const float*)d_in[9];
    const float* a1um_s = (const float*)d_in[10];
    const float* a1um_d = (const float*)d_in[11];
    const float* b1um   = (const float*)d_in[12];
    const float* w1mu_s = (const float*)d_in[13];
    const float* w1mu_d = (const float*)d_in[14];
    const float* a1mu_s = (const float*)d_in[15];
    const float* a1mu_d = (const float*)d_in[16];
    const float* b1mu   = (const float*)d_in[17];
    const float* w2um_s = (const float*)d_in[18];
    const float* w2um_d = (const float*)d_in[19];
    const float* a2um_s = (const float*)d_in[20];
    const float* a2um_d = (const float*)d_in[21];
    const float* b2um   = (const float*)d_in[22];
    const float* w2mu_s = (const float*)d_in[23];
    const float* w2mu_d = (const float*)d_in[24];
    const float* a2mu_s = (const float*)d_in[25];
    const float* a2mu_d = (const float*)d_in[26];
    const float* b2mu   = (const float*)d_in[27];
    const float* dw1    = (const float*)d_in[28];
    const float* db1    = (const float*)d_in[29];
    const float* dw2    = (const float*)d_in[30];
    const float* db2    = (const float*)d_in[31];
    float* out = (float*)d_out;

    float *hs1mu, *zu, *zm, *psu, *psm, *pu, *pm;
    float *su1, *su2, *sm1, *sm2;
    float *wa1, *wa2, *wa3, *wa4, *wb1, *wb2, *wb3, *wb4, *wfum, *wfmu, *bc;
    int *rp_um, *rp_mu, *csr_um, *csr_mu, *cnt, *bsum;
    cudaGetSymbolAddress((void**)&hs1mu, g_hs1mu);
    cudaGetSymbolAddress((void**)&zu,  g_zu);
    cudaGetSymbolAddress((void**)&zm,  g_zm);
    cudaGetSymbolAddress((void**)&psu, g_psu);
    cudaGetSymbolAddress((void**)&psm, g_psm);
    cudaGetSymbolAddress((void**)&pu,  g_pu);
    cudaGetSymbolAddress((void**)&pm,  g_pm);
    cudaGetSymbolAddress((void**)&su1, g_su1);
    cudaGetSymbolAddress((void**)&su2, g_su2);
    cudaGetSymbolAddress((void**)&sm1, g_sm1);
    cudaGetSymbolAddress((void**)&sm2, g_sm2);
    cudaGetSymbolAddress((void**)&wa1, g_wa1);
    cudaGetSymbolAddress((void**)&wa2, g_wa2);
    cudaGetSymbolAddress((void**)&wa3, g_wa3);
    cudaGetSymbolAddress((void**)&wa4, g_wa4);
    cudaGetSymbolAddress((void**)&wb1, g_wb1);
    cudaGetSymbolAddress((void**)&wb2, g_wb2);
    cudaGetSymbolAddress((void**)&wb3, g_wb3);
    cudaGetSymbolAddress((void**)&wb4, g_wb4);
    cudaGetSymbolAddress((void**)&wfum, g_wfum);
    cudaGetSymbolAddress((void**)&wfmu, g_wfmu);
    cudaGetSymbolAddress((void**)&bc,  g_bc);
    cudaGetSymbolAddress((void**)&rp_um, g_rp_um);
    cudaGetSymbolAddress((void**)&rp_mu, g_rp_mu);
    cudaGetSymbolAddress((void**)&csr_um, g_csr_um);
    cudaGetSymbolAddress((void**)&csr_mu, g_csr_mu);
    cudaGetSymbolAddress((void**)&cnt, g_cnt);
    cudaGetSymbolAddress((void**)&bsum, g_bsum);
    int* cnt_um = cnt;
    int* cnt_mu = cnt + NM;

    const int TB = 256;
    const int nb_um = ceil_div(NM, 1024), nb_mu = ceil_div(NU, 1024);

    // 1: zero degree counters
    cudaMemsetAsync(cnt, 0, (NM + NU) * sizeof(int));
    // 2: mega1 = sgemm(hs1mu) | histogram | all weight folds
    mega1_k<<<NB_MEGA1, 256>>>(xm, w1mu_s, hs1mu,
                               um_dst, mu_dst, cnt_um, cnt_mu,
                               w1um_s, a1um_s, w1mu_d, a1mu_d,
                               w1um_d, a1um_d, a1mu_s,
                               w2um_s, a2um_s, w2mu_d, a2mu_d,
                               w2um_d, a2um_d, w2mu_s, a2mu_s,
                               dw1, db1, b2um, b2mu,
                               wa1, wa2, wa3, wa4, wb1, wb2, wb3, wb4,
                               wfum, wfmu, bc);
    // 3: front2r = scores(xu) | scores(xm) | degree block-reduce
    front2r_k<<<NB_F2R, 256>>>(xu, xm, wa1, wa2, wa3, wa4,
                               su1, su2, sm1, sm2, cnt, bsum, nb_um);
    // 4-6: CSR scan + scatter
    scan2_k<<<1, 64>>>(bsum, nb_um, nb_mu);
    blkscan2_k<<<nb_um + nb_mu, 256>>>(cnt_um, rp_um, NM, nb_um, E, cnt_mu, rp_mu, NU, E, bsum);
    scatter2_k<<<ceil_div(E, TB), TB>>>(um_src, um_dst, cnt_um, csr_um,
                                        mu_src, mu_dst, cnt_mu, csr_mu, E);
    // 7: layer-1 aggregations (um aggregate+post fused -> zm | mu fused -> zu)
    fused_aggr1_k<<<NB_AGGR, 256>>>(rp_um, csr_um, su1, sm1, xu, w1um_s, b1um, zm,
                                    rp_mu, csr_mu, sm2, su2, hs1mu, b1mu, zu);
    // 8: proj64+scores for zu | zm
    proj2_k<<<NB_PROJ2, 256>>>(zu, wfum, wb1, wb2, psu, su1, su2,
                               zm, wfmu, wb3, wb4, psm, sm1, sm2);
    // 9: layer-2 aggregations (um | mu)
    fused_aggr2_k<<<NB_AGGR, 256>>>(rp_um, csr_um, su1, sm1, psu, pm,
                                    rp_mu, csr_mu, sm2, su2, psm, pu);
    // 10: decoder
    dec_edge_k<<<ceil_div(EL, TB), TB>>>(pu, pm, lab_u, lab_m, bc, dw2, db2, out, EL);
}